// round 2
// baseline (speedup 1.0000x reference)
#include <cuda_runtime.h>
#include <math.h>

#define D_MODEL 1024
#define SEQ     2048
#define BATCH   4
#define NTOK    (BATCH*SEQ)      // 8192
#define NHEAD   16
#define HDIM    64
#define DFF     4096

// ---------------- scratch (alloc-free: __device__ globals) ----------------
__device__ float g_normed[(size_t)NTOK * D_MODEL];        // 32 MB
__device__ float g_qkv   [(size_t)NTOK * 3 * D_MODEL];    // 96 MB
__device__ float g_attn  [(size_t)NTOK * D_MODEL];        // 32 MB
__device__ float g_x1    [(size_t)NTOK * D_MODEL];        // 32 MB
__device__ float g_h     [(size_t)NTOK * DFF];            // 128 MB

// ---------------- LayerNorm: one block per token, 256 thr, float4 ----------
__global__ void __launch_bounds__(256) ln_kernel(
    const float* __restrict__ x, const float* __restrict__ g,
    const float* __restrict__ b, float* __restrict__ y)
{
    int t = blockIdx.x;
    int tid = threadIdx.x;
    const float4* row = (const float4*)(x + (size_t)t * D_MODEL);
    float4 v = row[tid];                       // 256*4 = 1024
    float s  = v.x + v.y + v.z + v.w;
    float sq = v.x*v.x + v.y*v.y + v.z*v.z + v.w*v.w;
    #pragma unroll
    for (int o = 16; o > 0; o >>= 1) {
        s  += __shfl_xor_sync(0xffffffffu, s,  o);
        sq += __shfl_xor_sync(0xffffffffu, sq, o);
    }
    __shared__ float ss[8], ssq[8];
    int w = tid >> 5, l = tid & 31;
    if (l == 0) { ss[w] = s; ssq[w] = sq; }
    __syncthreads();
    if (w == 0) {
        s  = (l < 8) ? ss[l]  : 0.f;
        sq = (l < 8) ? ssq[l] : 0.f;
        #pragma unroll
        for (int o = 4; o > 0; o >>= 1) {
            s  += __shfl_xor_sync(0xffffffffu, s,  o);
            sq += __shfl_xor_sync(0xffffffffu, sq, o);
        }
        if (l == 0) { ss[0] = s; ssq[0] = sq; }
    }
    __syncthreads();
    float mean = ss[0] * (1.0f / D_MODEL);
    float var  = ssq[0] * (1.0f / D_MODEL) - mean * mean;
    float rstd = rsqrtf(var + 1e-5f);
    float4 gg = ((const float4*)g)[tid];
    float4 bb = ((const float4*)b)[tid];
    float4 o4;
    o4.x = (v.x - mean) * rstd * gg.x + bb.x;
    o4.y = (v.y - mean) * rstd * gg.y + bb.y;
    o4.z = (v.z - mean) * rstd * gg.z + bb.z;
    o4.w = (v.w - mean) * rstd * gg.w + bb.w;
    ((float4*)(y + (size_t)t * D_MODEL))[tid] = o4;
}

// ---------------- SGEMM: C[M,N] = A[M,K]@B[K,N] + bias (+epilogue) ----------
// BM=128, BN=128, BK=16, 256 threads, 8x8 microtile. Dims divide tiles exactly.
__device__ __forceinline__ float gelu_exact(float x) {
    return 0.5f * x * (1.0f + erff(x * 0.70710678118654752f));
}

template<int EPI>  // 0 = bias, 1 = bias+gelu, 2 = bias+residual
__global__ void __launch_bounds__(256) gemm_kernel(
    const float* __restrict__ A, const float* __restrict__ B,
    const float* __restrict__ bias, const float* __restrict__ Rsd,
    float* __restrict__ C, int M, int N, int K)
{
    __shared__ float As[16][128];   // transposed: As[k][m]
    __shared__ float Bs[16][128];   // Bs[k][n]
    int tid = threadIdx.x;
    int m0 = blockIdx.y * 128, n0 = blockIdx.x * 128;
    int ty = tid >> 4, tx = tid & 15;

    float acc[8][8];
    #pragma unroll
    for (int i = 0; i < 8; i++)
        #pragma unroll
        for (int j = 0; j < 8; j++) acc[i][j] = 0.f;

    int arow = tid >> 2, ac = (tid & 3) * 4;     // A: 64 rows/pass, 16 cols
    int brow = tid >> 5, bc = (tid & 31) * 4;    // B: 8 rows/pass, 128 cols
    const float* Ap = A + (size_t)(m0 + arow) * K + ac;
    const float* Bp = B + (size_t)brow * N + n0 + bc;

    for (int k0 = 0; k0 < K; k0 += 16) {
        float4 a0 = *(const float4*)(Ap);
        float4 a1 = *(const float4*)(Ap + (size_t)64 * K);
        float4 b0 = *(const float4*)(Bp);
        float4 b1 = *(const float4*)(Bp + (size_t)8 * N);
        Ap += 16;
        Bp += (size_t)16 * N;

        As[ac + 0][arow] = a0.x;  As[ac + 1][arow] = a0.y;
        As[ac + 2][arow] = a0.z;  As[ac + 3][arow] = a0.w;
        As[ac + 0][arow + 64] = a1.x;  As[ac + 1][arow + 64] = a1.y;
        As[ac + 2][arow + 64] = a1.z;  As[ac + 3][arow + 64] = a1.w;
        *(float4*)&Bs[brow][bc]     = b0;
        *(float4*)&Bs[brow + 8][bc] = b1;
        __syncthreads();

        #pragma unroll
        for (int kk = 0; kk < 16; kk++) {
            float a[8], bb[8];
            *(float4*)(a)     = *(const float4*)&As[kk][ty * 8];
            *(float4*)(a + 4) = *(const float4*)&As[kk][ty * 8 + 4];
            *(float4*)(bb)     = *(const float4*)&Bs[kk][tx * 8];
            *(float4*)(bb + 4) = *(const float4*)&Bs[kk][tx * 8 + 4];
            #pragma unroll
            for (int i = 0; i < 8; i++)
                #pragma unroll
                for (int j = 0; j < 8; j++)
                    acc[i][j] += a[i] * bb[j];
        }
        __syncthreads();
    }

    #pragma unroll
    for (int i = 0; i < 8; i++) {
        int m = m0 + ty * 8 + i;
        float* crow = C + (size_t)m * N + n0 + tx * 8;
        const float* rrow = (EPI == 2) ? (Rsd + (size_t)m * N + n0 + tx * 8) : nullptr;
        #pragma unroll
        for (int j4 = 0; j4 < 8; j4 += 4) {
            float4 bb = *(const float4*)(bias + n0 + tx * 8 + j4);
            float4 r;
            r.x = acc[i][j4 + 0] + bb.x;
            r.y = acc[i][j4 + 1] + bb.y;
            r.z = acc[i][j4 + 2] + bb.z;
            r.w = acc[i][j4 + 3] + bb.w;
            if (EPI == 1) {
                r.x = gelu_exact(r.x); r.y = gelu_exact(r.y);
                r.z = gelu_exact(r.z); r.w = gelu_exact(r.w);
            }
            if (EPI == 2) {
                float4 rr = *(const float4*)(rrow + j4);
                r.x += rr.x; r.y += rr.y; r.z += rr.z; r.w += rr.w;
            }
            *(float4*)(crow + j4) = r;
        }
    }
}

// ---------------- Flash attention: BQ=64, BK=64, causal, online softmax ----
// qkv layout: [tok, 3*1024], Q at col h*64, K at 1024+h*64, V at 2048+h*64.
// Grid: (32 q-tiles, 16 heads, 4 batches), 256 threads = 16x16, 4x4 microtiles.
#define FPAD 68
__global__ void __launch_bounds__(256) flash_kernel(
    const float* __restrict__ qkv, float* __restrict__ outp)
{
    extern __shared__ float sm[];
    float* QsT = sm;                  // [d][r]  (64 x FPAD)
    float* KsT = sm + 64 * FPAD;      // [d][k]
    float* Vs  = sm + 2 * 64 * FPAD;  // [k][d]
    float* PsT = sm + 3 * 64 * FPAD;  // [k][r]

    int tid = threadIdx.x;
    int tx = tid & 15, ty = tid >> 4;
    int qt = blockIdx.x, h = blockIdx.y, b = blockIdx.z;
    int tok0 = b * SEQ + qt * 64;
    size_t qbase = (size_t)tok0 * 3072 + h * 64;

    // load Q tile (64 tokens x 64 dims) transposed into QsT[d][r]
    #pragma unroll
    for (int p = 0; p < 4; p++) {
        int f = tid + p * 256;
        int r = f >> 4, c = (f & 15) * 4;
        float4 v = *(const float4*)(qkv + qbase + (size_t)r * 3072 + c);
        QsT[(c + 0) * FPAD + r] = v.x;
        QsT[(c + 1) * FPAD + r] = v.y;
        QsT[(c + 2) * FPAD + r] = v.z;
        QsT[(c + 3) * FPAD + r] = v.w;
    }

    float m_i[4], l_i[4], o[4][4];
    #pragma unroll
    for (int i = 0; i < 4; i++) {
        m_i[i] = -1e30f; l_i[i] = 0.f;
        #pragma unroll
        for (int j = 0; j < 4; j++) o[i][j] = 0.f;
    }

    int nkt = qt + 1;                  // causal: key tiles 0..qt
    for (int kt = 0; kt < nkt; kt++) {
        int ktok0 = b * SEQ + kt * 64;
        size_t kbase = (size_t)ktok0 * 3072 + 1024 + h * 64;
        size_t vbase = kbase + 1024;
        __syncthreads();
        #pragma unroll
        for (int p = 0; p < 4; p++) {
            int f = tid + p * 256;
            int r = f >> 4, c = (f & 15) * 4;
            float4 kv = *(const float4*)(qkv + kbase + (size_t)r * 3072 + c);
            KsT[(c + 0) * FPAD + r] = kv.x;
            KsT[(c + 1) * FPAD + r] = kv.y;
            KsT[(c + 2) * FPAD + r] = kv.z;
            KsT[(c + 3) * FPAD + r] = kv.w;
            float4 vv = *(const float4*)(qkv + vbase + (size_t)r * 3072 + c);
            *(float4*)&Vs[r * FPAD + c] = vv;
        }
        __syncthreads();

        // S = Q @ K^T (4x4 per thread)
        float s[4][4];
        #pragma unroll
        for (int i = 0; i < 4; i++)
            #pragma unroll
            for (int j = 0; j < 4; j++) s[i][j] = 0.f;
        #pragma unroll 4
        for (int d = 0; d < 64; d++) {
            float4 qa = *(const float4*)&QsT[d * FPAD + ty * 4];
            float4 kb = *(const float4*)&KsT[d * FPAD + tx * 4];
            float qr[4] = {qa.x, qa.y, qa.z, qa.w};
            float kc[4] = {kb.x, kb.y, kb.z, kb.w};
            #pragma unroll
            for (int i = 0; i < 4; i++)
                #pragma unroll
                for (int j = 0; j < 4; j++)
                    s[i][j] += qr[i] * kc[j];
        }
        const float scale = 0.125f;  // 1/sqrt(64)
        bool diag = (kt == qt);
        #pragma unroll
        for (int i = 0; i < 4; i++)
            #pragma unroll
            for (int j = 0; j < 4; j++) {
                s[i][j] *= scale;
                if (diag && (tx * 4 + j) > (ty * 4 + i)) s[i][j] = -1e30f;
            }

        // online softmax per row (row shared by the 16 tx lanes of same ty)
        #pragma unroll
        for (int i = 0; i < 4; i++) {
            float mn = fmaxf(fmaxf(s[i][0], s[i][1]), fmaxf(s[i][2], s[i][3]));
            #pragma unroll
            for (int off = 8; off > 0; off >>= 1)
                mn = fmaxf(mn, __shfl_xor_sync(0xffffffffu, mn, off));
            float mt = fmaxf(m_i[i], mn);
            float fac = __expf(m_i[i] - mt);
            m_i[i] = mt;
            float rs = 0.f;
            #pragma unroll
            for (int j = 0; j < 4; j++) {
                float p = __expf(s[i][j] - mt);
                PsT[(tx * 4 + j) * FPAD + ty * 4 + i] = p;
                rs += p;
            }
            #pragma unroll
            for (int off = 8; off > 0; off >>= 1)
                rs += __shfl_xor_sync(0xffffffffu, rs, off);
            l_i[i] = l_i[i] * fac + rs;
            #pragma unroll
            for (int j = 0; j < 4; j++) o[i][j] *= fac;
        }
        __syncthreads();

        // O += P @ V
        #pragma unroll 4
        for (int k = 0; k < 64; k++) {
            float4 pa = *(const float4*)&PsT[k * FPAD + ty * 4];
            float4 va = *(const float4*)&Vs[k * FPAD + tx * 4];
            float pr[4] = {pa.x, pa.y, pa.z, pa.w};
            float vv[4] = {va.x, va.y, va.z, va.w};
            #pragma unroll
            for (int i = 0; i < 4; i++)
                #pragma unroll
                for (int j = 0; j < 4; j++)
                    o[i][j] += pr[i] * vv[j];
        }
    }

    // write O / l  ->  attn[(b*SEQ + q)*1024 + h*64 + d]
    #pragma unroll
    for (int i = 0; i < 4; i++) {
        float inv = 1.0f / l_i[i];
        int tok = tok0 + ty * 4 + i;
        float4 w;
        w.x = o[i][0] * inv; w.y = o[i][1] * inv;
        w.z = o[i][2] * inv; w.w = o[i][3] * inv;
        *(float4*)(outp + (size_t)tok * D_MODEL + h * 64 + tx * 4) = w;
    }
}

// ---------------- launcher ----------------
extern "C" void kernel_launch(void* const* d_in, const int* in_sizes, int n_in,
                              void* d_out, int out_size)
{
    const float* x      = (const float*)d_in[0];
    const float* qkv_w  = (const float*)d_in[1];
    const float* qkv_b  = (const float*)d_in[2];
    const float* out_w  = (const float*)d_in[3];
    const float* out_b  = (const float*)d_in[4];
    const float* ffn1_w = (const float*)d_in[5];
    const float* ffn1_b = (const float*)d_in[6];
    const float* ffn2_w = (const float*)d_in[7];
    const float* ffn2_b = (const float*)d_in[8];
    const float* ln1_g  = (const float*)d_in[9];
    const float* ln1_b  = (const float*)d_in[10];
    const float* ln2_g  = (const float*)d_in[11];
    const float* ln2_b  = (const float*)d_in[12];
    float* outp = (float*)d_out;

    float *normed, *qkvb, *attn, *x1, *hb;
    cudaGetSymbolAddress((void**)&normed, g_normed);
    cudaGetSymbolAddress((void**)&qkvb,   g_qkv);
    cudaGetSymbolAddress((void**)&attn,   g_attn);
    cudaGetSymbolAddress((void**)&x1,     g_x1);
    cudaGetSymbolAddress((void**)&hb,     g_h);

    const int FLASH_SMEM = 4 * 64 * FPAD * 4;  // 69632 B
    cudaFuncSetAttribute(flash_kernel,
                         cudaFuncAttributeMaxDynamicSharedMemorySize, FLASH_SMEM);

    // 1) LN1
    ln_kernel<<<NTOK, 256>>>(x, ln1_g, ln1_b, normed);
    // 2) QKV projection: [8192,1024] @ [1024,3072]
    gemm_kernel<0><<<dim3(3 * D_MODEL / 128, NTOK / 128), 256>>>(
        normed, qkv_w, qkv_b, nullptr, qkvb, NTOK, 3 * D_MODEL, D_MODEL);
    // 3) causal flash attention
    flash_kernel<<<dim3(SEQ / 64, NHEAD, BATCH), 256, FLASH_SMEM>>>(qkvb, attn);
    // 4) out projection + residual(x) -> x1
    gemm_kernel<2><<<dim3(D_MODEL / 128, NTOK / 128), 256>>>(
        attn, out_w, out_b, x, x1, NTOK, D_MODEL, D_MODEL);
    // 5) LN2
    ln_kernel<<<NTOK, 256>>>(x1, ln2_g, ln2_b, normed);
    // 6) FFN1 + GELU
    gemm_kernel<1><<<dim3(DFF / 128, NTOK / 128), 256>>>(
        normed, ffn1_w, ffn1_b, nullptr, hb, NTOK, DFF, D_MODEL);
    // 7) FFN2 + residual(x1) -> out
    gemm_kernel<2><<<dim3(D_MODEL / 128, NTOK / 128), 256>>>(
        hb, ffn2_w, ffn2_b, x1, outp, NTOK, D_MODEL, DFF);
}

// round 3
// speedup vs baseline: 2.0547x; 2.0547x over previous
#include <cuda_runtime.h>
#include <math.h>
#include <stdint.h>

#define D_MODEL 1024
#define SEQ     2048
#define BATCH   4
#define NTOK    (BATCH*SEQ)      // 8192
#define NHEAD   16
#define HDIM    64
#define DFF     4096

// ---------------- scratch (alloc-free: __device__ globals) ----------------
__device__ float g_normed[(size_t)NTOK * D_MODEL];        // 32 MB
__device__ float g_qkv   [(size_t)NTOK * 3 * D_MODEL];    // 96 MB
__device__ float g_attn  [(size_t)NTOK * D_MODEL];        // 32 MB
__device__ float g_x1    [(size_t)NTOK * D_MODEL];        // 32 MB
__device__ float g_h     [(size_t)NTOK * DFF];            // 128 MB

// ---------------- LayerNorm: one block per token, 256 thr, float4 ----------
__global__ void __launch_bounds__(256) ln_kernel(
    const float* __restrict__ x, const float* __restrict__ g,
    const float* __restrict__ b, float* __restrict__ y)
{
    int t = blockIdx.x;
    int tid = threadIdx.x;
    const float4* row = (const float4*)(x + (size_t)t * D_MODEL);
    float4 v = row[tid];                       // 256*4 = 1024
    float s  = v.x + v.y + v.z + v.w;
    float sq = v.x*v.x + v.y*v.y + v.z*v.z + v.w*v.w;
    #pragma unroll
    for (int o = 16; o > 0; o >>= 1) {
        s  += __shfl_xor_sync(0xffffffffu, s,  o);
        sq += __shfl_xor_sync(0xffffffffu, sq, o);
    }
    __shared__ float ss[8], ssq[8];
    int w = tid >> 5, l = tid & 31;
    if (l == 0) { ss[w] = s; ssq[w] = sq; }
    __syncthreads();
    if (w == 0) {
        s  = (l < 8) ? ss[l]  : 0.f;
        sq = (l < 8) ? ssq[l] : 0.f;
        #pragma unroll
        for (int o = 4; o > 0; o >>= 1) {
            s  += __shfl_xor_sync(0xffffffffu, s,  o);
            sq += __shfl_xor_sync(0xffffffffu, sq, o);
        }
        if (l == 0) { ss[0] = s; ssq[0] = sq; }
    }
    __syncthreads();
    float mean = ss[0] * (1.0f / D_MODEL);
    float var  = ssq[0] * (1.0f / D_MODEL) - mean * mean;
    float rstd = rsqrtf(var + 1e-5f);
    float4 gg = ((const float4*)g)[tid];
    float4 bb = ((const float4*)b)[tid];
    float4 o4;
    o4.x = (v.x - mean) * rstd * gg.x + bb.x;
    o4.y = (v.y - mean) * rstd * gg.y + bb.y;
    o4.z = (v.z - mean) * rstd * gg.z + bb.z;
    o4.w = (v.w - mean) * rstd * gg.w + bb.w;
    ((float4*)(y + (size_t)t * D_MODEL))[tid] = o4;
}

// ---------------- tf32 tensor-core GEMM ------------------------------------
// C[M,N] = A[M,K] @ B[K,N] + bias (+GELU | +residual)
// CTA tile 128x128, BK=16, 256 threads = 8 warps (2x4), warp tile 64x32.
// mma.sync.aligned.m16n8k8.row.col.f32.tf32.tf32.f32, fp32 accumulate.
// Smem padding chosen so all fragment loads are bank-conflict-free:
//   A stored [m][k] stride 20; B stored [k][n] stride 136.
__device__ __forceinline__ float gelu_exact(float x) {
    return 0.5f * x * (1.0f + erff(x * 0.70710678118654752f));
}
__device__ __forceinline__ uint32_t f2tf32(float x) {
    uint32_t r;
    asm("cvt.rna.tf32.f32 %0, %1;" : "=r"(r) : "f"(x));
    return r;
}

#define AS_STRIDE 20
#define BS_STRIDE 136

template<int EPI>  // 0 = bias, 1 = bias+gelu, 2 = bias+residual
__global__ void __launch_bounds__(256, 2) gemm_tf32(
    const float* __restrict__ A, const float* __restrict__ B,
    const float* __restrict__ bias, const float* __restrict__ Rsd,
    float* __restrict__ C, int M, int N, int K)
{
    __shared__ uint32_t As[2][128 * AS_STRIDE];   // 2 x 10240 B
    __shared__ uint32_t Bs[2][16 * BS_STRIDE];    // 2 x  8704 B

    const int tid  = threadIdx.x;
    const int lane = tid & 31, warp = tid >> 5;
    const int wm = warp >> 2, wn = warp & 3;       // warp grid 2 x 4
    const int g  = lane >> 2, t4 = lane & 3;
    const int m0 = blockIdx.y * 128, n0 = blockIdx.x * 128;

    float acc[4][4][4];
    #pragma unroll
    for (int i = 0; i < 4; i++)
        #pragma unroll
        for (int j = 0; j < 4; j++)
            #pragma unroll
            for (int r = 0; r < 4; r++) acc[i][j][r] = 0.f;

    // gmem staging assignment
    const int ar = tid >> 2, ac = (tid & 3) * 4;   // A: rows ar, ar+64; cols ac..ac+3
    const int br = tid >> 5, bc = (tid & 31) * 4;  // B: rows br, br+8;  cols bc..bc+3
    const float* Ap = A + (size_t)(m0 + ar) * K + ac;
    const float* Bp = B + (size_t)br * N + n0 + bc;

    float4 ra0 = *(const float4*)(Ap);
    float4 ra1 = *(const float4*)(Ap + (size_t)64 * K);
    float4 rb0 = *(const float4*)(Bp);
    float4 rb1 = *(const float4*)(Bp + (size_t)8 * N);

    // store tile 0 into buffer 0
    {
        uint32_t* a = As[0];
        a[(ar     ) * AS_STRIDE + ac + 0] = f2tf32(ra0.x);
        a[(ar     ) * AS_STRIDE + ac + 1] = f2tf32(ra0.y);
        a[(ar     ) * AS_STRIDE + ac + 2] = f2tf32(ra0.z);
        a[(ar     ) * AS_STRIDE + ac + 3] = f2tf32(ra0.w);
        a[(ar + 64) * AS_STRIDE + ac + 0] = f2tf32(ra1.x);
        a[(ar + 64) * AS_STRIDE + ac + 1] = f2tf32(ra1.y);
        a[(ar + 64) * AS_STRIDE + ac + 2] = f2tf32(ra1.z);
        a[(ar + 64) * AS_STRIDE + ac + 3] = f2tf32(ra1.w);
        uint32_t* bsm = Bs[0];
        bsm[(br    ) * BS_STRIDE + bc + 0] = f2tf32(rb0.x);
        bsm[(br    ) * BS_STRIDE + bc + 1] = f2tf32(rb0.y);
        bsm[(br    ) * BS_STRIDE + bc + 2] = f2tf32(rb0.z);
        bsm[(br    ) * BS_STRIDE + bc + 3] = f2tf32(rb0.w);
        bsm[(br + 8) * BS_STRIDE + bc + 0] = f2tf32(rb1.x);
        bsm[(br + 8) * BS_STRIDE + bc + 1] = f2tf32(rb1.y);
        bsm[(br + 8) * BS_STRIDE + bc + 2] = f2tf32(rb1.z);
        bsm[(br + 8) * BS_STRIDE + bc + 3] = f2tf32(rb1.w);
    }
    __syncthreads();

    int buf = 0;
    for (int k0 = 0; k0 < K; k0 += 16) {
        const bool more = (k0 + 16) < K;
        if (more) {
            Ap += 16; Bp += (size_t)16 * N;
            ra0 = *(const float4*)(Ap);
            ra1 = *(const float4*)(Ap + (size_t)64 * K);
            rb0 = *(const float4*)(Bp);
            rb1 = *(const float4*)(Bp + (size_t)8 * N);
        }

        const uint32_t* a = As[buf];
        const uint32_t* bsm = Bs[buf];
        #pragma unroll
        for (int ks = 0; ks < 2; ks++) {
            const int kb = ks * 8;
            uint32_t bfrag[4][2], afrag[4][4];
            #pragma unroll
            for (int nt = 0; nt < 4; nt++) {
                int col = wn * 32 + nt * 8 + g;
                bfrag[nt][0] = bsm[(kb + t4    ) * BS_STRIDE + col];
                bfrag[nt][1] = bsm[(kb + t4 + 4) * BS_STRIDE + col];
            }
            #pragma unroll
            for (int mt = 0; mt < 4; mt++) {
                int row = wm * 64 + mt * 16 + g;
                afrag[mt][0] = a[(row    ) * AS_STRIDE + kb + t4];
                afrag[mt][1] = a[(row + 8) * AS_STRIDE + kb + t4];
                afrag[mt][2] = a[(row    ) * AS_STRIDE + kb + t4 + 4];
                afrag[mt][3] = a[(row + 8) * AS_STRIDE + kb + t4 + 4];
            }
            #pragma unroll
            for (int mt = 0; mt < 4; mt++)
                #pragma unroll
                for (int nt = 0; nt < 4; nt++)
                    asm volatile(
                        "mma.sync.aligned.m16n8k8.row.col.f32.tf32.tf32.f32 "
                        "{%0,%1,%2,%3}, {%4,%5,%6,%7}, {%8,%9}, {%0,%1,%2,%3};"
                        : "+f"(acc[mt][nt][0]), "+f"(acc[mt][nt][1]),
                          "+f"(acc[mt][nt][2]), "+f"(acc[mt][nt][3])
                        : "r"(afrag[mt][0]), "r"(afrag[mt][1]),
                          "r"(afrag[mt][2]), "r"(afrag[mt][3]),
                          "r"(bfrag[nt][0]), "r"(bfrag[nt][1]));
        }

        if (more) {
            const int nb = buf ^ 1;
            uint32_t* an = As[nb];
            an[(ar     ) * AS_STRIDE + ac + 0] = f2tf32(ra0.x);
            an[(ar     ) * AS_STRIDE + ac + 1] = f2tf32(ra0.y);
            an[(ar     ) * AS_STRIDE + ac + 2] = f2tf32(ra0.z);
            an[(ar     ) * AS_STRIDE + ac + 3] = f2tf32(ra0.w);
            an[(ar + 64) * AS_STRIDE + ac + 0] = f2tf32(ra1.x);
            an[(ar + 64) * AS_STRIDE + ac + 1] = f2tf32(ra1.y);
            an[(ar + 64) * AS_STRIDE + ac + 2] = f2tf32(ra1.z);
            an[(ar + 64) * AS_STRIDE + ac + 3] = f2tf32(ra1.w);
            uint32_t* bn = Bs[nb];
            bn[(br    ) * BS_STRIDE + bc + 0] = f2tf32(rb0.x);
            bn[(br    ) * BS_STRIDE + bc + 1] = f2tf32(rb0.y);
            bn[(br    ) * BS_STRIDE + bc + 2] = f2tf32(rb0.z);
            bn[(br    ) * BS_STRIDE + bc + 3] = f2tf32(rb0.w);
            bn[(br + 8) * BS_STRIDE + bc + 0] = f2tf32(rb1.x);
            bn[(br + 8) * BS_STRIDE + bc + 1] = f2tf32(rb1.y);
            bn[(br + 8) * BS_STRIDE + bc + 2] = f2tf32(rb1.z);
            bn[(br + 8) * BS_STRIDE + bc + 3] = f2tf32(rb1.w);
            buf = nb;
        }
        __syncthreads();
    }

    // epilogue: fragment layout c0:(g, 2*t4) c1:(g, 2*t4+1) c2:(g+8, ..) c3
    #pragma unroll
    for (int mt = 0; mt < 4; mt++) {
        #pragma unroll
        for (int nt = 0; nt < 4; nt++) {
            int row = m0 + wm * 64 + mt * 16 + g;
            int col = n0 + wn * 32 + nt * 8 + t4 * 2;
            float2 bb = *(const float2*)(bias + col);
            #pragma unroll
            for (int h = 0; h < 2; h++) {
                int r = row + h * 8;
                float2 v;
                v.x = acc[mt][nt][h * 2 + 0] + bb.x;
                v.y = acc[mt][nt][h * 2 + 1] + bb.y;
                if (EPI == 1) { v.x = gelu_exact(v.x); v.y = gelu_exact(v.y); }
                if (EPI == 2) {
                    float2 rr = *(const float2*)(Rsd + (size_t)r * N + col);
                    v.x += rr.x; v.y += rr.y;
                }
                *(float2*)(C + (size_t)r * N + col) = v;
            }
        }
    }
}

// ---------------- Flash attention: BQ=64, BK=64, causal, online softmax ----
// qkv layout: [tok, 3*1024], Q at col h*64, K at 1024+h*64, V at 2048+h*64.
// Grid: (32 q-tiles, 16 heads, 4 batches), 256 threads = 16x16, 4x4 microtiles.
#define FPAD 68
__global__ void __launch_bounds__(256) flash_kernel(
    const float* __restrict__ qkv, float* __restrict__ outp)
{
    extern __shared__ float sm[];
    float* QsT = sm;                  // [d][r]  (64 x FPAD)
    float* KsT = sm + 64 * FPAD;      // [d][k]
    float* Vs  = sm + 2 * 64 * FPAD;  // [k][d]
    float* PsT = sm + 3 * 64 * FPAD;  // [k][r]

    int tid = threadIdx.x;
    int tx = tid & 15, ty = tid >> 4;
    int qt = blockIdx.x, h = blockIdx.y, b = blockIdx.z;
    int tok0 = b * SEQ + qt * 64;
    size_t qbase = (size_t)tok0 * 3072 + h * 64;

    #pragma unroll
    for (int p = 0; p < 4; p++) {
        int f = tid + p * 256;
        int r = f >> 4, c = (f & 15) * 4;
        float4 v = *(const float4*)(qkv + qbase + (size_t)r * 3072 + c);
        QsT[(c + 0) * FPAD + r] = v.x;
        QsT[(c + 1) * FPAD + r] = v.y;
        QsT[(c + 2) * FPAD + r] = v.z;
        QsT[(c + 3) * FPAD + r] = v.w;
    }

    float m_i[4], l_i[4], o[4][4];
    #pragma unroll
    for (int i = 0; i < 4; i++) {
        m_i[i] = -1e30f; l_i[i] = 0.f;
        #pragma unroll
        for (int j = 0; j < 4; j++) o[i][j] = 0.f;
    }

    int nkt = qt + 1;
    for (int kt = 0; kt < nkt; kt++) {
        int ktok0 = b * SEQ + kt * 64;
        size_t kbase = (size_t)ktok0 * 3072 + 1024 + h * 64;
        size_t vbase = kbase + 1024;
        __syncthreads();
        #pragma unroll
        for (int p = 0; p < 4; p++) {
            int f = tid + p * 256;
            int r = f >> 4, c = (f & 15) * 4;
            float4 kv = *(const float4*)(qkv + kbase + (size_t)r * 3072 + c);
            KsT[(c + 0) * FPAD + r] = kv.x;
            KsT[(c + 1) * FPAD + r] = kv.y;
            KsT[(c + 2) * FPAD + r] = kv.z;
            KsT[(c + 3) * FPAD + r] = kv.w;
            float4 vv = *(const float4*)(qkv + vbase + (size_t)r * 3072 + c);
            *(float4*)&Vs[r * FPAD + c] = vv;
        }
        __syncthreads();

        float s[4][4];
        #pragma unroll
        for (int i = 0; i < 4; i++)
            #pragma unroll
            for (int j = 0; j < 4; j++) s[i][j] = 0.f;
        #pragma unroll 4
        for (int d = 0; d < 64; d++) {
            float4 qa = *(const float4*)&QsT[d * FPAD + ty * 4];
            float4 kb = *(const float4*)&KsT[d * FPAD + tx * 4];
            float qr[4] = {qa.x, qa.y, qa.z, qa.w};
            float kc[4] = {kb.x, kb.y, kb.z, kb.w};
            #pragma unroll
            for (int i = 0; i < 4; i++)
                #pragma unroll
                for (int j = 0; j < 4; j++)
                    s[i][j] += qr[i] * kc[j];
        }
        const float scale = 0.125f;
        bool diag = (kt == qt);
        #pragma unroll
        for (int i = 0; i < 4; i++)
            #pragma unroll
            for (int j = 0; j < 4; j++) {
                s[i][j] *= scale;
                if (diag && (tx * 4 + j) > (ty * 4 + i)) s[i][j] = -1e30f;
            }

        #pragma unroll
        for (int i = 0; i < 4; i++) {
            float mn = fmaxf(fmaxf(s[i][0], s[i][1]), fmaxf(s[i][2], s[i][3]));
            #pragma unroll
            for (int off = 8; off > 0; off >>= 1)
                mn = fmaxf(mn, __shfl_xor_sync(0xffffffffu, mn, off));
            float mt = fmaxf(m_i[i], mn);
            float fac = __expf(m_i[i] - mt);
            m_i[i] = mt;
            float rs = 0.f;
            #pragma unroll
            for (int j = 0; j < 4; j++) {
                float p = __expf(s[i][j] - mt);
                PsT[(tx * 4 + j) * FPAD + ty * 4 + i] = p;
                rs += p;
            }
            #pragma unroll
            for (int off = 8; off > 0; off >>= 1)
                rs += __shfl_xor_sync(0xffffffffu, rs, off);
            l_i[i] = l_i[i] * fac + rs;
            #pragma unroll
            for (int j = 0; j < 4; j++) o[i][j] *= fac;
        }
        __syncthreads();

        #pragma unroll 4
        for (int k = 0; k < 64; k++) {
            float4 pa = *(const float4*)&PsT[k * FPAD + ty * 4];
            float4 va = *(const float4*)&Vs[k * FPAD + tx * 4];
            float pr[4] = {pa.x, pa.y, pa.z, pa.w};
            float vv[4] = {va.x, va.y, va.z, va.w};
            #pragma unroll
            for (int i = 0; i < 4; i++)
                #pragma unroll
                for (int j = 0; j < 4; j++)
                    o[i][j] += pr[i] * vv[j];
        }
    }

    #pragma unroll
    for (int i = 0; i < 4; i++) {
        float inv = 1.0f / l_i[i];
        int tok = tok0 + ty * 4 + i;
        float4 w;
        w.x = o[i][0] * inv; w.y = o[i][1] * inv;
        w.z = o[i][2] * inv; w.w = o[i][3] * inv;
        *(float4*)(outp + (size_t)tok * D_MODEL + h * 64 + tx * 4) = w;
    }
}

// ---------------- launcher ----------------
extern "C" void kernel_launch(void* const* d_in, const int* in_sizes, int n_in,
                              void* d_out, int out_size)
{
    const float* x      = (const float*)d_in[0];
    const float* qkv_w  = (const float*)d_in[1];
    const float* qkv_b  = (const float*)d_in[2];
    const float* out_w  = (const float*)d_in[3];
    const float* out_b  = (const float*)d_in[4];
    const float* ffn1_w = (const float*)d_in[5];
    const float* ffn1_b = (const float*)d_in[6];
    const float* ffn2_w = (const float*)d_in[7];
    const float* ffn2_b = (const float*)d_in[8];
    const float* ln1_g  = (const float*)d_in[9];
    const float* ln1_b  = (const float*)d_in[10];
    const float* ln2_g  = (const float*)d_in[11];
    const float* ln2_b  = (const float*)d_in[12];
    float* outp = (float*)d_out;

    float *normed, *qkvb, *attn, *x1, *hb;
    cudaGetSymbolAddress((void**)&normed, g_normed);
    cudaGetSymbolAddress((void**)&qkvb,   g_qkv);
    cudaGetSymbolAddress((void**)&attn,   g_attn);
    cudaGetSymbolAddress((void**)&x1,     g_x1);
    cudaGetSymbolAddress((void**)&hb,     g_h);

    const int FLASH_SMEM = 4 * 64 * FPAD * 4;  // 69632 B
    cudaFuncSetAttribute(flash_kernel,
                         cudaFuncAttributeMaxDynamicSharedMemorySize, FLASH_SMEM);

    // 1) LN1
    ln_kernel<<<NTOK, 256>>>(x, ln1_g, ln1_b, normed);
    // 2) QKV projection: [8192,1024] @ [1024,3072]
    gemm_tf32<0><<<dim3(3 * D_MODEL / 128, NTOK / 128), 256>>>(
        normed, qkv_w, qkv_b, nullptr, qkvb, NTOK, 3 * D_MODEL, D_MODEL);
    // 3) causal flash attention
    flash_kernel<<<dim3(SEQ / 64, NHEAD, BATCH), 256, FLASH_SMEM>>>(qkvb, attn);
    // 4) out projection + residual(x) -> x1
    gemm_tf32<2><<<dim3(D_MODEL / 128, NTOK / 128), 256>>>(
        attn, out_w, out_b, x, x1, NTOK, D_MODEL, D_MODEL);
    // 5) LN2
    ln_kernel<<<NTOK, 256>>>(x1, ln2_g, ln2_b, normed);
    // 6) FFN1 + GELU
    gemm_tf32<1><<<dim3(DFF / 128, NTOK / 128), 256>>>(
        normed, ffn1_w, ffn1_b, nullptr, hb, NTOK, DFF, D_MODEL);
    // 7) FFN2 + residual(x1) -> out
    gemm_tf32<2><<<dim3(D_MODEL / 128, NTOK / 128), 256>>>(
        hb, ffn2_w, ffn2_b, x1, outp, NTOK, D_MODEL, DFF);
}

// round 4
// speedup vs baseline: 2.6883x; 1.3084x over previous
#include <cuda_runtime.h>
#include <cuda_bf16.h>
#include <math.h>
#include <stdint.h>

#define D_MODEL 1024
#define SEQ     2048
#define BATCH   4
#define NTOK    (BATCH*SEQ)      // 8192
#define NHEAD   16
#define HDIM    64
#define DFF     4096

// ---------------- scratch (alloc-free: __device__ globals) ----------------
__device__ float g_normed[(size_t)NTOK * D_MODEL];        // 32 MB
__device__ float g_qkv   [(size_t)NTOK * 3 * D_MODEL];    // 96 MB
__device__ float g_attn  [(size_t)NTOK * D_MODEL];        // 32 MB
__device__ float g_x1    [(size_t)NTOK * D_MODEL];        // 32 MB
__device__ float g_h     [(size_t)NTOK * DFF];            // 128 MB

// ---------------- LayerNorm: one block per token, 256 thr, float4 ----------
__global__ void __launch_bounds__(256) ln_kernel(
    const float* __restrict__ x, const float* __restrict__ g,
    const float* __restrict__ b, float* __restrict__ y)
{
    int t = blockIdx.x;
    int tid = threadIdx.x;
    const float4* row = (const float4*)(x + (size_t)t * D_MODEL);
    float4 v = row[tid];                       // 256*4 = 1024
    float s  = v.x + v.y + v.z + v.w;
    float sq = v.x*v.x + v.y*v.y + v.z*v.z + v.w*v.w;
    #pragma unroll
    for (int o = 16; o > 0; o >>= 1) {
        s  += __shfl_xor_sync(0xffffffffu, s,  o);
        sq += __shfl_xor_sync(0xffffffffu, sq, o);
    }
    __shared__ float ss[8], ssq[8];
    int w = tid >> 5, l = tid & 31;
    if (l == 0) { ss[w] = s; ssq[w] = sq; }
    __syncthreads();
    if (w == 0) {
        s  = (l < 8) ? ss[l]  : 0.f;
        sq = (l < 8) ? ssq[l] : 0.f;
        #pragma unroll
        for (int o = 4; o > 0; o >>= 1) {
            s  += __shfl_xor_sync(0xffffffffu, s,  o);
            sq += __shfl_xor_sync(0xffffffffu, sq, o);
        }
        if (l == 0) { ss[0] = s; ssq[0] = sq; }
    }
    __syncthreads();
    float mean = ss[0] * (1.0f / D_MODEL);
    float var  = ssq[0] * (1.0f / D_MODEL) - mean * mean;
    float rstd = rsqrtf(var + 1e-5f);
    float4 gg = ((const float4*)g)[tid];
    float4 bb = ((const float4*)b)[tid];
    float4 o4;
    o4.x = (v.x - mean) * rstd * gg.x + bb.x;
    o4.y = (v.y - mean) * rstd * gg.y + bb.y;
    o4.z = (v.z - mean) * rstd * gg.z + bb.z;
    o4.w = (v.w - mean) * rstd * gg.w + bb.w;
    ((float4*)(y + (size_t)t * D_MODEL))[tid] = o4;
}

// ---------------- bf16 tensor-core GEMM -------------------------------------
// C[M,N] = A[M,K] @ B[K,N] + bias (+GELU | +residual), fp32 accumulate.
// CTA tile 128x128, BK=32, 256 threads = 8 warps (2x4), warp tile 64x32.
// mma.sync.m16n8k16.row.col.f32.bf16.bf16.f32; smem fed via ldmatrix.
// A smem: [m][k], row stride 40 bf16 (80B) -> LDSM conflict-free.
// B smem: [k][n], row stride 136 bf16 (272B) -> LDSM conflict-free.
__device__ __forceinline__ float gelu_exact(float x) {
    return 0.5f * x * (1.0f + erff(x * 0.70710678118654752f));
}
__device__ __forceinline__ uint2 f4_to_bf16x4(float4 v) {
    __nv_bfloat162 lo = __floats2bfloat162_rn(v.x, v.y);
    __nv_bfloat162 hi = __floats2bfloat162_rn(v.z, v.w);
    uint2 r;
    r.x = *(uint32_t*)&lo;
    r.y = *(uint32_t*)&hi;
    return r;
}
__device__ __forceinline__ void ldsm_x4(uint32_t& r0, uint32_t& r1,
                                        uint32_t& r2, uint32_t& r3,
                                        const void* p) {
    uint32_t a = (uint32_t)__cvta_generic_to_shared(p);
    asm volatile("ldmatrix.sync.aligned.m8n8.x4.shared.b16 {%0,%1,%2,%3}, [%4];"
                 : "=r"(r0), "=r"(r1), "=r"(r2), "=r"(r3) : "r"(a));
}
__device__ __forceinline__ void ldsm_x4_t(uint32_t& r0, uint32_t& r1,
                                          uint32_t& r2, uint32_t& r3,
                                          const void* p) {
    uint32_t a = (uint32_t)__cvta_generic_to_shared(p);
    asm volatile("ldmatrix.sync.aligned.m8n8.x4.trans.shared.b16 {%0,%1,%2,%3}, [%4];"
                 : "=r"(r0), "=r"(r1), "=r"(r2), "=r"(r3) : "r"(a));
}

#define ASTR 40
#define BSTR 136

template<int EPI>  // 0 = bias, 1 = bias+gelu, 2 = bias+residual
__global__ void __launch_bounds__(256, 2) gemm_bf16(
    const float* __restrict__ A, const float* __restrict__ B,
    const float* __restrict__ bias, const float* __restrict__ Rsd,
    float* __restrict__ C, int M, int N, int K)
{
    __shared__ __nv_bfloat16 As[2][128 * ASTR];   // 2 x 10240 B
    __shared__ __nv_bfloat16 Bs[2][32 * BSTR];    // 2 x  8704 B

    const int tid  = threadIdx.x;
    const int lane = tid & 31, warp = tid >> 5;
    const int wm = warp >> 2, wn = warp & 3;       // warp grid 2 x 4
    const int g  = lane >> 2, t4 = lane & 3;
    const int l15 = lane & 15, lhi = (lane >> 4) << 3;
    const int m0 = blockIdx.y * 128, n0 = blockIdx.x * 128;

    float acc[4][4][4];
    #pragma unroll
    for (int i = 0; i < 4; i++)
        #pragma unroll
        for (int j = 0; j < 4; j++)
            #pragma unroll
            for (int r = 0; r < 4; r++) acc[i][j][r] = 0.f;

    // gmem staging: A rows ar+{0,32,64,96} cols ac..ac+3 (of BK=32)
    //               B rows br+{0,8,16,24}  cols bc..bc+3 (of 128)
    const int ar = tid >> 3, ac = (tid & 7) * 4;
    const int br = tid >> 5, bc = (tid & 31) * 4;
    const float* Ap = A + (size_t)(m0 + ar) * K + ac;
    const float* Bp = B + (size_t)br * N + n0 + bc;

    uint2 sa[4], sb[4];
    #pragma unroll
    for (int p = 0; p < 4; p++) {
        sa[p] = f4_to_bf16x4(*(const float4*)(Ap + (size_t)(p * 32) * K));
        sb[p] = f4_to_bf16x4(*(const float4*)(Bp + (size_t)(p * 8) * N));
    }
    #pragma unroll
    for (int p = 0; p < 4; p++) {
        *(uint2*)&As[0][(ar + p * 32) * ASTR + ac] = sa[p];
        *(uint2*)&Bs[0][(br + p * 8) * BSTR + bc]  = sb[p];
    }
    __syncthreads();

    int buf = 0;
    for (int k0 = 0; k0 < K; k0 += 32) {
        const bool more = (k0 + 32) < K;
        if (more) {
            Ap += 32; Bp += (size_t)32 * N;
            #pragma unroll
            for (int p = 0; p < 4; p++) {
                sa[p] = f4_to_bf16x4(*(const float4*)(Ap + (size_t)(p * 32) * K));
                sb[p] = f4_to_bf16x4(*(const float4*)(Bp + (size_t)(p * 8) * N));
            }
        }

        const __nv_bfloat16* a  = As[buf];
        const __nv_bfloat16* bs = Bs[buf];
        #pragma unroll
        for (int ks = 0; ks < 2; ks++) {
            const int kb = ks * 16;
            uint32_t af[4][4];
            #pragma unroll
            for (int mt = 0; mt < 4; mt++)
                ldsm_x4(af[mt][0], af[mt][1], af[mt][2], af[mt][3],
                        &a[(wm * 64 + mt * 16 + l15) * ASTR + kb + lhi]);
            uint32_t bf_[4][2];
            #pragma unroll
            for (int ntp = 0; ntp < 2; ntp++) {
                uint32_t r0, r1, r2, r3;
                ldsm_x4_t(r0, r1, r2, r3,
                          &bs[(kb + l15) * BSTR + wn * 32 + ntp * 16 + lhi]);
                bf_[2 * ntp][0] = r0;     bf_[2 * ntp][1] = r1;
                bf_[2 * ntp + 1][0] = r2; bf_[2 * ntp + 1][1] = r3;
            }
            #pragma unroll
            for (int mt = 0; mt < 4; mt++)
                #pragma unroll
                for (int nt = 0; nt < 4; nt++)
                    asm volatile(
                        "mma.sync.aligned.m16n8k16.row.col.f32.bf16.bf16.f32 "
                        "{%0,%1,%2,%3}, {%4,%5,%6,%7}, {%8,%9}, {%0,%1,%2,%3};"
                        : "+f"(acc[mt][nt][0]), "+f"(acc[mt][nt][1]),
                          "+f"(acc[mt][nt][2]), "+f"(acc[mt][nt][3])
                        : "r"(af[mt][0]), "r"(af[mt][1]),
                          "r"(af[mt][2]), "r"(af[mt][3]),
                          "r"(bf_[nt][0]), "r"(bf_[nt][1]));
        }

        if (more) {
            const int nb = buf ^ 1;
            #pragma unroll
            for (int p = 0; p < 4; p++) {
                *(uint2*)&As[nb][(ar + p * 32) * ASTR + ac] = sa[p];
                *(uint2*)&Bs[nb][(br + p * 8) * BSTR + bc]  = sb[p];
            }
            buf = nb;
        }
        __syncthreads();
    }

    // epilogue: fragment c0:(g, 2t4) c1:(g, 2t4+1) c2:(g+8, 2t4) c3:(g+8, 2t4+1)
    #pragma unroll
    for (int mt = 0; mt < 4; mt++) {
        #pragma unroll
        for (int nt = 0; nt < 4; nt++) {
            int row = m0 + wm * 64 + mt * 16 + g;
            int col = n0 + wn * 32 + nt * 8 + t4 * 2;
            float2 bb = *(const float2*)(bias + col);
            #pragma unroll
            for (int h = 0; h < 2; h++) {
                int r = row + h * 8;
                float2 v;
                v.x = acc[mt][nt][h * 2 + 0] + bb.x;
                v.y = acc[mt][nt][h * 2 + 1] + bb.y;
                if (EPI == 1) { v.x = gelu_exact(v.x); v.y = gelu_exact(v.y); }
                if (EPI == 2) {
                    float2 rr = *(const float2*)(Rsd + (size_t)r * N + col);
                    v.x += rr.x; v.y += rr.y;
                }
                *(float2*)(C + (size_t)r * N + col) = v;
            }
        }
    }
}

// ---------------- Flash attention: BQ=64, BK=64, causal, online softmax ----
// qkv layout: [tok, 3*1024], Q at col h*64, K at 1024+h*64, V at 2048+h*64.
// Grid: (32 q-tiles, 16 heads, 4 batches), 256 threads = 16x16, 4x4 microtiles.
#define FPAD 68
__global__ void __launch_bounds__(256) flash_kernel(
    const float* __restrict__ qkv, float* __restrict__ outp)
{
    extern __shared__ float sm[];
    float* QsT = sm;                  // [d][r]  (64 x FPAD)
    float* KsT = sm + 64 * FPAD;      // [d][k]
    float* Vs  = sm + 2 * 64 * FPAD;  // [k][d]
    float* PsT = sm + 3 * 64 * FPAD;  // [k][r]

    int tid = threadIdx.x;
    int tx = tid & 15, ty = tid >> 4;
    int qt = blockIdx.x, h = blockIdx.y, b = blockIdx.z;
    int tok0 = b * SEQ + qt * 64;
    size_t qbase = (size_t)tok0 * 3072 + h * 64;

    #pragma unroll
    for (int p = 0; p < 4; p++) {
        int f = tid + p * 256;
        int r = f >> 4, c = (f & 15) * 4;
        float4 v = *(const float4*)(qkv + qbase + (size_t)r * 3072 + c);
        QsT[(c + 0) * FPAD + r] = v.x;
        QsT[(c + 1) * FPAD + r] = v.y;
        QsT[(c + 2) * FPAD + r] = v.z;
        QsT[(c + 3) * FPAD + r] = v.w;
    }

    float m_i[4], l_i[4], o[4][4];
    #pragma unroll
    for (int i = 0; i < 4; i++) {
        m_i[i] = -1e30f; l_i[i] = 0.f;
        #pragma unroll
        for (int j = 0; j < 4; j++) o[i][j] = 0.f;
    }

    int nkt = qt + 1;
    for (int kt = 0; kt < nkt; kt++) {
        int ktok0 = b * SEQ + kt * 64;
        size_t kbase = (size_t)ktok0 * 3072 + 1024 + h * 64;
        size_t vbase = kbase + 1024;
        __syncthreads();
        #pragma unroll
        for (int p = 0; p < 4; p++) {
            int f = tid + p * 256;
            int r = f >> 4, c = (f & 15) * 4;
            float4 kv = *(const float4*)(qkv + kbase + (size_t)r * 3072 + c);
            KsT[(c + 0) * FPAD + r] = kv.x;
            KsT[(c + 1) * FPAD + r] = kv.y;
            KsT[(c + 2) * FPAD + r] = kv.z;
            KsT[(c + 3) * FPAD + r] = kv.w;
            float4 vv = *(const float4*)(qkv + vbase + (size_t)r * 3072 + c);
            *(float4*)&Vs[r * FPAD + c] = vv;
        }
        __syncthreads();

        float s[4][4];
        #pragma unroll
        for (int i = 0; i < 4; i++)
            #pragma unroll
            for (int j = 0; j < 4; j++) s[i][j] = 0.f;
        #pragma unroll 4
        for (int d = 0; d < 64; d++) {
            float4 qa = *(const float4*)&QsT[d * FPAD + ty * 4];
            float4 kb = *(const float4*)&KsT[d * FPAD + tx * 4];
            float qr[4] = {qa.x, qa.y, qa.z, qa.w};
            float kc[4] = {kb.x, kb.y, kb.z, kb.w};
            #pragma unroll
            for (int i = 0; i < 4; i++)
                #pragma unroll
                for (int j = 0; j < 4; j++)
                    s[i][j] += qr[i] * kc[j];
        }
        const float scale = 0.125f;
        bool diag = (kt == qt);
        #pragma unroll
        for (int i = 0; i < 4; i++)
            #pragma unroll
            for (int j = 0; j < 4; j++) {
                s[i][j] *= scale;
                if (diag && (tx * 4 + j) > (ty * 4 + i)) s[i][j] = -1e30f;
            }

        #pragma unroll
        for (int i = 0; i < 4; i++) {
            float mn = fmaxf(fmaxf(s[i][0], s[i][1]), fmaxf(s[i][2], s[i][3]));
            #pragma unroll
            for (int off = 8; off > 0; off >>= 1)
                mn = fmaxf(mn, __shfl_xor_sync(0xffffffffu, mn, off));
            float mt = fmaxf(m_i[i], mn);
            float fac = __expf(m_i[i] - mt);
            m_i[i] = mt;
            float rs = 0.f;
            #pragma unroll
            for (int j = 0; j < 4; j++) {
                float p = __expf(s[i][j] - mt);
                PsT[(tx * 4 + j) * FPAD + ty * 4 + i] = p;
                rs += p;
            }
            #pragma unroll
            for (int off = 8; off > 0; off >>= 1)
                rs += __shfl_xor_sync(0xffffffffu, rs, off);
            l_i[i] = l_i[i] * fac + rs;
            #pragma unroll
            for (int j = 0; j < 4; j++) o[i][j] *= fac;
        }
        __syncthreads();

        #pragma unroll 4
        for (int k = 0; k < 64; k++) {
            float4 pa = *(const float4*)&PsT[k * FPAD + ty * 4];
            float4 va = *(const float4*)&Vs[k * FPAD + tx * 4];
            float pr[4] = {pa.x, pa.y, pa.z, pa.w};
            float vv[4] = {va.x, va.y, va.z, va.w};
            #pragma unroll
            for (int i = 0; i < 4; i++)
                #pragma unroll
                for (int j = 0; j < 4; j++)
                    o[i][j] += pr[i] * vv[j];
        }
    }

    #pragma unroll
    for (int i = 0; i < 4; i++) {
        float inv = 1.0f / l_i[i];
        int tok = tok0 + ty * 4 + i;
        float4 w;
        w.x = o[i][0] * inv; w.y = o[i][1] * inv;
        w.z = o[i][2] * inv; w.w = o[i][3] * inv;
        *(float4*)(outp + (size_t)tok * D_MODEL + h * 64 + tx * 4) = w;
    }
}

// ---------------- launcher ----------------
extern "C" void kernel_launch(void* const* d_in, const int* in_sizes, int n_in,
                              void* d_out, int out_size)
{
    const float* x      = (const float*)d_in[0];
    const float* qkv_w  = (const float*)d_in[1];
    const float* qkv_b  = (const float*)d_in[2];
    const float* out_w  = (const float*)d_in[3];
    const float* out_b  = (const float*)d_in[4];
    const float* ffn1_w = (const float*)d_in[5];
    const float* ffn1_b = (const float*)d_in[6];
    const float* ffn2_w = (const float*)d_in[7];
    const float* ffn2_b = (const float*)d_in[8];
    const float* ln1_g  = (const float*)d_in[9];
    const float* ln1_b  = (const float*)d_in[10];
    const float* ln2_g  = (const float*)d_in[11];
    const float* ln2_b  = (const float*)d_in[12];
    float* outp = (float*)d_out;

    float *normed, *qkvb, *attn, *x1, *hb;
    cudaGetSymbolAddress((void**)&normed, g_normed);
    cudaGetSymbolAddress((void**)&qkvb,   g_qkv);
    cudaGetSymbolAddress((void**)&attn,   g_attn);
    cudaGetSymbolAddress((void**)&x1,     g_x1);
    cudaGetSymbolAddress((void**)&hb,     g_h);

    const int FLASH_SMEM = 4 * 64 * FPAD * 4;  // 69632 B
    cudaFuncSetAttribute(flash_kernel,
                         cudaFuncAttributeMaxDynamicSharedMemorySize, FLASH_SMEM);

    // 1) LN1
    ln_kernel<<<NTOK, 256>>>(x, ln1_g, ln1_b, normed);
    // 2) QKV projection: [8192,1024] @ [1024,3072]
    gemm_bf16<0><<<dim3(3 * D_MODEL / 128, NTOK / 128), 256>>>(
        normed, qkv_w, qkv_b, nullptr, qkvb, NTOK, 3 * D_MODEL, D_MODEL);
    // 3) causal flash attention
    flash_kernel<<<dim3(SEQ / 64, NHEAD, BATCH), 256, FLASH_SMEM>>>(qkvb, attn);
    // 4) out projection + residual(x) -> x1
    gemm_bf16<2><<<dim3(D_MODEL / 128, NTOK / 128), 256>>>(
        attn, out_w, out_b, x, x1, NTOK, D_MODEL, D_MODEL);
    // 5) LN2
    ln_kernel<<<NTOK, 256>>>(x1, ln2_g, ln2_b, normed);
    // 6) FFN1 + GELU
    gemm_bf16<1><<<dim3(DFF / 128, NTOK / 128), 256>>>(
        normed, ffn1_w, ffn1_b, nullptr, hb, NTOK, DFF, D_MODEL);
    // 7) FFN2 + residual(x1) -> out
    gemm_bf16<2><<<dim3(D_MODEL / 128, NTOK / 128), 256>>>(
        hb, ffn2_w, ffn2_b, x1, outp, NTOK, D_MODEL, DFF);
}

// round 5
// speedup vs baseline: 4.3568x; 1.6207x over previous
#include <cuda_runtime.h>
#include <cuda_bf16.h>
#include <math.h>
#include <stdint.h>

#define D_MODEL 1024
#define SEQ     2048
#define BATCH   4
#define NTOK    (BATCH*SEQ)      // 8192
#define NHEAD   16
#define HDIM    64
#define DFF     4096

// ---------------- scratch (alloc-free: __device__ globals) ----------------
__device__ float g_normed[(size_t)NTOK * D_MODEL];        // 32 MB
__device__ float g_qkv   [(size_t)NTOK * 3 * D_MODEL];    // 96 MB
__device__ float g_attn  [(size_t)NTOK * D_MODEL];        // 32 MB
__device__ float g_x1    [(size_t)NTOK * D_MODEL];        // 32 MB
__device__ float g_h     [(size_t)NTOK * DFF];            // 128 MB

// ---------------- LayerNorm ----------
__global__ void __launch_bounds__(256) ln_kernel(
    const float* __restrict__ x, const float* __restrict__ g,
    const float* __restrict__ b, float* __restrict__ y)
{
    int t = blockIdx.x;
    int tid = threadIdx.x;
    const float4* row = (const float4*)(x + (size_t)t * D_MODEL);
    float4 v = row[tid];
    float s  = v.x + v.y + v.z + v.w;
    float sq = v.x*v.x + v.y*v.y + v.z*v.z + v.w*v.w;
    #pragma unroll
    for (int o = 16; o > 0; o >>= 1) {
        s  += __shfl_xor_sync(0xffffffffu, s,  o);
        sq += __shfl_xor_sync(0xffffffffu, sq, o);
    }
    __shared__ float ss[8], ssq[8];
    int w = tid >> 5, l = tid & 31;
    if (l == 0) { ss[w] = s; ssq[w] = sq; }
    __syncthreads();
    if (w == 0) {
        s  = (l < 8) ? ss[l]  : 0.f;
        sq = (l < 8) ? ssq[l] : 0.f;
        #pragma unroll
        for (int o = 4; o > 0; o >>= 1) {
            s  += __shfl_xor_sync(0xffffffffu, s,  o);
            sq += __shfl_xor_sync(0xffffffffu, sq, o);
        }
        if (l == 0) { ss[0] = s; ssq[0] = sq; }
    }
    __syncthreads();
    float mean = ss[0] * (1.0f / D_MODEL);
    float var  = ssq[0] * (1.0f / D_MODEL) - mean * mean;
    float rstd = rsqrtf(var + 1e-5f);
    float4 gg = ((const float4*)g)[tid];
    float4 bb = ((const float4*)b)[tid];
    float4 o4;
    o4.x = (v.x - mean) * rstd * gg.x + bb.x;
    o4.y = (v.y - mean) * rstd * gg.y + bb.y;
    o4.z = (v.z - mean) * rstd * gg.z + bb.z;
    o4.w = (v.w - mean) * rstd * gg.w + bb.w;
    ((float4*)(y + (size_t)t * D_MODEL))[tid] = o4;
}

// ---------------- bf16 tensor-core GEMM (unchanged from R3) -----------------
__device__ __forceinline__ float gelu_exact(float x) {
    return 0.5f * x * (1.0f + erff(x * 0.70710678118654752f));
}
__device__ __forceinline__ uint2 f4_to_bf16x4(float4 v) {
    __nv_bfloat162 lo = __floats2bfloat162_rn(v.x, v.y);
    __nv_bfloat162 hi = __floats2bfloat162_rn(v.z, v.w);
    uint2 r;
    r.x = *(uint32_t*)&lo;
    r.y = *(uint32_t*)&hi;
    return r;
}
__device__ __forceinline__ uint32_t f2tf32(float x) {
    uint32_t r;
    asm("cvt.rna.tf32.f32 %0, %1;" : "=r"(r) : "f"(x));
    return r;
}
__device__ __forceinline__ void ldsm_x4(uint32_t& r0, uint32_t& r1,
                                        uint32_t& r2, uint32_t& r3,
                                        const void* p) {
    uint32_t a = (uint32_t)__cvta_generic_to_shared(p);
    asm volatile("ldmatrix.sync.aligned.m8n8.x4.shared.b16 {%0,%1,%2,%3}, [%4];"
                 : "=r"(r0), "=r"(r1), "=r"(r2), "=r"(r3) : "r"(a));
}
__device__ __forceinline__ void ldsm_x4_t(uint32_t& r0, uint32_t& r1,
                                          uint32_t& r2, uint32_t& r3,
                                          const void* p) {
    uint32_t a = (uint32_t)__cvta_generic_to_shared(p);
    asm volatile("ldmatrix.sync.aligned.m8n8.x4.trans.shared.b16 {%0,%1,%2,%3}, [%4];"
                 : "=r"(r0), "=r"(r1), "=r"(r2), "=r"(r3) : "r"(a));
}

#define ASTR 40
#define BSTR 136

template<int EPI>  // 0 = bias, 1 = bias+gelu, 2 = bias+residual
__global__ void __launch_bounds__(256, 2) gemm_bf16(
    const float* __restrict__ A, const float* __restrict__ B,
    const float* __restrict__ bias, const float* __restrict__ Rsd,
    float* __restrict__ C, int M, int N, int K)
{
    __shared__ __nv_bfloat16 As[2][128 * ASTR];
    __shared__ __nv_bfloat16 Bs[2][32 * BSTR];

    const int tid  = threadIdx.x;
    const int lane = tid & 31, warp = tid >> 5;
    const int wm = warp >> 2, wn = warp & 3;
    const int g  = lane >> 2, t4 = lane & 3;
    const int l15 = lane & 15, lhi = (lane >> 4) << 3;
    const int m0 = blockIdx.y * 128, n0 = blockIdx.x * 128;

    float acc[4][4][4];
    #pragma unroll
    for (int i = 0; i < 4; i++)
        #pragma unroll
        for (int j = 0; j < 4; j++)
            #pragma unroll
            for (int r = 0; r < 4; r++) acc[i][j][r] = 0.f;

    const int ar = tid >> 3, ac = (tid & 7) * 4;
    const int br = tid >> 5, bc = (tid & 31) * 4;
    const float* Ap = A + (size_t)(m0 + ar) * K + ac;
    const float* Bp = B + (size_t)br * N + n0 + bc;

    uint2 sa[4], sb[4];
    #pragma unroll
    for (int p = 0; p < 4; p++) {
        sa[p] = f4_to_bf16x4(*(const float4*)(Ap + (size_t)(p * 32) * K));
        sb[p] = f4_to_bf16x4(*(const float4*)(Bp + (size_t)(p * 8) * N));
    }
    #pragma unroll
    for (int p = 0; p < 4; p++) {
        *(uint2*)&As[0][(ar + p * 32) * ASTR + ac] = sa[p];
        *(uint2*)&Bs[0][(br + p * 8) * BSTR + bc]  = sb[p];
    }
    __syncthreads();

    int buf = 0;
    for (int k0 = 0; k0 < K; k0 += 32) {
        const bool more = (k0 + 32) < K;
        if (more) {
            Ap += 32; Bp += (size_t)32 * N;
            #pragma unroll
            for (int p = 0; p < 4; p++) {
                sa[p] = f4_to_bf16x4(*(const float4*)(Ap + (size_t)(p * 32) * K));
                sb[p] = f4_to_bf16x4(*(const float4*)(Bp + (size_t)(p * 8) * N));
            }
        }

        const __nv_bfloat16* a  = As[buf];
        const __nv_bfloat16* bs = Bs[buf];
        #pragma unroll
        for (int ks = 0; ks < 2; ks++) {
            const int kb = ks * 16;
            uint32_t af[4][4];
            #pragma unroll
            for (int mt = 0; mt < 4; mt++)
                ldsm_x4(af[mt][0], af[mt][1], af[mt][2], af[mt][3],
                        &a[(wm * 64 + mt * 16 + l15) * ASTR + kb + lhi]);
            uint32_t bf_[4][2];
            #pragma unroll
            for (int ntp = 0; ntp < 2; ntp++) {
                uint32_t r0, r1, r2, r3;
                ldsm_x4_t(r0, r1, r2, r3,
                          &bs[(kb + l15) * BSTR + wn * 32 + ntp * 16 + lhi]);
                bf_[2 * ntp][0] = r0;     bf_[2 * ntp][1] = r1;
                bf_[2 * ntp + 1][0] = r2; bf_[2 * ntp + 1][1] = r3;
            }
            #pragma unroll
            for (int mt = 0; mt < 4; mt++)
                #pragma unroll
                for (int nt = 0; nt < 4; nt++)
                    asm volatile(
                        "mma.sync.aligned.m16n8k16.row.col.f32.bf16.bf16.f32 "
                        "{%0,%1,%2,%3}, {%4,%5,%6,%7}, {%8,%9}, {%0,%1,%2,%3};"
                        : "+f"(acc[mt][nt][0]), "+f"(acc[mt][nt][1]),
                          "+f"(acc[mt][nt][2]), "+f"(acc[mt][nt][3])
                        : "r"(af[mt][0]), "r"(af[mt][1]),
                          "r"(af[mt][2]), "r"(af[mt][3]),
                          "r"(bf_[nt][0]), "r"(bf_[nt][1]));
        }

        if (more) {
            const int nb = buf ^ 1;
            #pragma unroll
            for (int p = 0; p < 4; p++) {
                *(uint2*)&As[nb][(ar + p * 32) * ASTR + ac] = sa[p];
                *(uint2*)&Bs[nb][(br + p * 8) * BSTR + bc]  = sb[p];
            }
            buf = nb;
        }
        __syncthreads();
    }

    #pragma unroll
    for (int mt = 0; mt < 4; mt++) {
        #pragma unroll
        for (int nt = 0; nt < 4; nt++) {
            int row = m0 + wm * 64 + mt * 16 + g;
            int col = n0 + wn * 32 + nt * 8 + t4 * 2;
            float2 bb = *(const float2*)(bias + col);
            #pragma unroll
            for (int h = 0; h < 2; h++) {
                int r = row + h * 8;
                float2 v;
                v.x = acc[mt][nt][h * 2 + 0] + bb.x;
                v.y = acc[mt][nt][h * 2 + 1] + bb.y;
                if (EPI == 1) { v.x = gelu_exact(v.x); v.y = gelu_exact(v.y); }
                if (EPI == 2) {
                    float2 rr = *(const float2*)(Rsd + (size_t)r * N + col);
                    v.x += rr.x; v.y += rr.y;
                }
                *(float2*)(C + (size_t)r * N + col) = v;
            }
        }
    }
}

// ---------------- Flash attention, tf32 tensor cores ------------------------
// BQ=128 q rows/CTA, BK=64 keys/iter. 8 warps; warp w owns rows w*16..w*16+15.
// Q pre-scaled by 0.125, held in registers as tf32 A-fragments.
// KsT[d][key] stride 72 (tf32 bits), Vs[key][d] stride 72 (tf32 bits).
// P reuses Q's smem region: Ps[row][key] stride 68 (tf32 bits).
// mma.m16n8k8.tf32; softmax on C-fragments (2 rows/thread, shfl over t4 quad).
#define FQ   128
#define FK   64
#define QSTR 68
#define KSTR 72
#define FLASH_SMEM ((FQ*QSTR + FK*KSTR + FK*KSTR) * 4)   // 71680 B

__global__ void __launch_bounds__(256, 2) flash_tc(
    const float* __restrict__ qkv, float* __restrict__ outp)
{
    extern __shared__ uint32_t smu[];
    uint32_t* QP  = smu;                    // Q (scaled fp32 bits), then P (tf32)
    uint32_t* KsT = smu + FQ * QSTR;        // [64 d][KSTR]
    uint32_t* Vs  = KsT + FK * KSTR;        // [64 key][KSTR]

    const int tid  = threadIdx.x;
    const int lane = tid & 31, w = tid >> 5;
    const int g = lane >> 2, t4 = lane & 3;
    const int qt = (SEQ / FQ - 1) - blockIdx.x;   // heavy tiles first
    const int h  = blockIdx.y, b = blockIdx.z;
    const int tok0 = b * SEQ + qt * FQ;
    const int mrow = w * 16 + g;

    // ---- load Q tile (scaled) ----
    {
        size_t qbase = (size_t)tok0 * 3072 + h * 64;
        #pragma unroll
        for (int p = 0; p < 8; p++) {
            int f = tid + p * 256;
            int r = f >> 4, c = (f & 15) * 4;
            float4 v = *(const float4*)(qkv + qbase + (size_t)r * 3072 + c);
            uint32_t* dst = &QP[r * QSTR + c];
            dst[0] = __float_as_uint(v.x * 0.125f);
            dst[1] = __float_as_uint(v.y * 0.125f);
            dst[2] = __float_as_uint(v.z * 0.125f);
            dst[3] = __float_as_uint(v.w * 0.125f);
        }
    }
    __syncthreads();

    // ---- Q fragments to registers (tf32) ----
    uint32_t qf[8][4];
    #pragma unroll
    for (int ks = 0; ks < 8; ks++) {
        int kb = ks * 8;
        qf[ks][0] = f2tf32(__uint_as_float(QP[(mrow    ) * QSTR + kb + t4]));
        qf[ks][1] = f2tf32(__uint_as_float(QP[(mrow + 8) * QSTR + kb + t4]));
        qf[ks][2] = f2tf32(__uint_as_float(QP[(mrow    ) * QSTR + kb + t4 + 4]));
        qf[ks][3] = f2tf32(__uint_as_float(QP[(mrow + 8) * QSTR + kb + t4 + 4]));
    }

    float m0r = -1e30f, m1r = -1e30f, l0 = 0.f, l1 = 0.f;
    float of[8][4];
    #pragma unroll
    for (int nf = 0; nf < 8; nf++)
        #pragma unroll
        for (int j = 0; j < 4; j++) of[nf][j] = 0.f;

    const int qrow0 = qt * FQ + mrow;      // sequence-local query rows
    const int qrow1 = qrow0 + 8;
    const int nkt = 2 * qt + 2;

    for (int kt = 0; kt < nkt; kt++) {
        __syncthreads();   // prior PV reads of Vs/Ps done (iter0: Q frag reads done)

        // ---- load K (transposed, conflict-free STS) and V ----
        {
            int ktok0 = b * SEQ + kt * FK;
            size_t kbase = (size_t)ktok0 * 3072 + 1024 + h * 64;
            size_t vbase = kbase + 1024;
            #pragma unroll
            for (int p = 0; p < 4; p++) {
                int f = tid + p * 256;
                int kr = f & 63, kc = (f >> 6) * 4;    // key-major for K transpose
                float4 kv = *(const float4*)(qkv + kbase + (size_t)kr * 3072 + kc);
                KsT[(kc + 0) * KSTR + kr] = f2tf32(kv.x);
                KsT[(kc + 1) * KSTR + kr] = f2tf32(kv.y);
                KsT[(kc + 2) * KSTR + kr] = f2tf32(kv.z);
                KsT[(kc + 3) * KSTR + kr] = f2tf32(kv.w);
                int vr = f >> 4, vc = (f & 15) * 4;    // row-major coalesced for V
                float4 vv = *(const float4*)(qkv + vbase + (size_t)vr * 3072 + vc);
                uint4 vb;
                vb.x = f2tf32(vv.x); vb.y = f2tf32(vv.y);
                vb.z = f2tf32(vv.z); vb.w = f2tf32(vv.w);
                *(uint4*)&Vs[vr * KSTR + vc] = vb;
            }
        }
        __syncthreads();

        // ---- S = Q @ K^T ----
        float sc[8][4];
        #pragma unroll
        for (int nf = 0; nf < 8; nf++)
            #pragma unroll
            for (int j = 0; j < 4; j++) sc[nf][j] = 0.f;
        #pragma unroll
        for (int ks = 0; ks < 8; ks++) {
            int kb = ks * 8;
            uint32_t bf[8][2];
            #pragma unroll
            for (int nf = 0; nf < 8; nf++) {
                bf[nf][0] = KsT[(kb + t4    ) * KSTR + nf * 8 + g];
                bf[nf][1] = KsT[(kb + t4 + 4) * KSTR + nf * 8 + g];
            }
            #pragma unroll
            for (int nf = 0; nf < 8; nf++)
                asm volatile(
                    "mma.sync.aligned.m16n8k8.row.col.f32.tf32.tf32.f32 "
                    "{%0,%1,%2,%3}, {%4,%5,%6,%7}, {%8,%9}, {%0,%1,%2,%3};"
                    : "+f"(sc[nf][0]), "+f"(sc[nf][1]),
                      "+f"(sc[nf][2]), "+f"(sc[nf][3])
                    : "r"(qf[ks][0]), "r"(qf[ks][1]),
                      "r"(qf[ks][2]), "r"(qf[ks][3]),
                      "r"(bf[nf][0]), "r"(bf[nf][1]));
        }

        // ---- causal mask (only the two diagonal-overlapping tiles) ----
        if (kt >= 2 * qt) {
            #pragma unroll
            for (int nf = 0; nf < 8; nf++) {
                int k0 = kt * FK + nf * 8 + 2 * t4;
                if (k0     > qrow0) sc[nf][0] = -1e30f;
                if (k0 + 1 > qrow0) sc[nf][1] = -1e30f;
                if (k0     > qrow1) sc[nf][2] = -1e30f;
                if (k0 + 1 > qrow1) sc[nf][3] = -1e30f;
            }
        }

        // ---- online softmax ----
        float mx0 = -1e30f, mx1 = -1e30f;
        #pragma unroll
        for (int nf = 0; nf < 8; nf++) {
            mx0 = fmaxf(mx0, fmaxf(sc[nf][0], sc[nf][1]));
            mx1 = fmaxf(mx1, fmaxf(sc[nf][2], sc[nf][3]));
        }
        mx0 = fmaxf(mx0, __shfl_xor_sync(0xffffffffu, mx0, 1));
        mx0 = fmaxf(mx0, __shfl_xor_sync(0xffffffffu, mx0, 2));
        mx1 = fmaxf(mx1, __shfl_xor_sync(0xffffffffu, mx1, 1));
        mx1 = fmaxf(mx1, __shfl_xor_sync(0xffffffffu, mx1, 2));
        float nm0 = fmaxf(m0r, mx0), nm1 = fmaxf(m1r, mx1);
        float fac0 = __expf(m0r - nm0), fac1 = __expf(m1r - nm1);
        m0r = nm0; m1r = nm1;

        float rs0 = 0.f, rs1 = 0.f;
        #pragma unroll
        for (int nf = 0; nf < 8; nf++) {
            float p00 = __expf(sc[nf][0] - nm0);
            float p01 = __expf(sc[nf][1] - nm0);
            float p10 = __expf(sc[nf][2] - nm1);
            float p11 = __expf(sc[nf][3] - nm1);
            rs0 += p00 + p01;
            rs1 += p10 + p11;
            int colb = nf * 8 + 2 * t4;
            uint2 w0; w0.x = f2tf32(p00); w0.y = f2tf32(p01);
            uint2 w1; w1.x = f2tf32(p10); w1.y = f2tf32(p11);
            *(uint2*)&QP[(mrow    ) * QSTR + colb] = w0;
            *(uint2*)&QP[(mrow + 8) * QSTR + colb] = w1;
        }
        rs0 += __shfl_xor_sync(0xffffffffu, rs0, 1);
        rs0 += __shfl_xor_sync(0xffffffffu, rs0, 2);
        rs1 += __shfl_xor_sync(0xffffffffu, rs1, 1);
        rs1 += __shfl_xor_sync(0xffffffffu, rs1, 2);
        l0 = l0 * fac0 + rs0;
        l1 = l1 * fac1 + rs1;
        #pragma unroll
        for (int nf = 0; nf < 8; nf++) {
            of[nf][0] *= fac0; of[nf][1] *= fac0;
            of[nf][2] *= fac1; of[nf][3] *= fac1;
        }
        __syncthreads();

        // ---- O += P @ V ----
        #pragma unroll
        for (int ks = 0; ks < 8; ks++) {
            int kb = ks * 8;
            uint32_t af[4];
            af[0] = QP[(mrow    ) * QSTR + kb + t4];
            af[1] = QP[(mrow + 8) * QSTR + kb + t4];
            af[2] = QP[(mrow    ) * QSTR + kb + t4 + 4];
            af[3] = QP[(mrow + 8) * QSTR + kb + t4 + 4];
            uint32_t bf[8][2];
            #pragma unroll
            for (int nf = 0; nf < 8; nf++) {
                bf[nf][0] = Vs[(kb + t4    ) * KSTR + nf * 8 + g];
                bf[nf][1] = Vs[(kb + t4 + 4) * KSTR + nf * 8 + g];
            }
            #pragma unroll
            for (int nf = 0; nf < 8; nf++)
                asm volatile(
                    "mma.sync.aligned.m16n8k8.row.col.f32.tf32.tf32.f32 "
                    "{%0,%1,%2,%3}, {%4,%5,%6,%7}, {%8,%9}, {%0,%1,%2,%3};"
                    : "+f"(of[nf][0]), "+f"(of[nf][1]),
                      "+f"(of[nf][2]), "+f"(of[nf][3])
                    : "r"(af[0]), "r"(af[1]), "r"(af[2]), "r"(af[3]),
                      "r"(bf[nf][0]), "r"(bf[nf][1]));
        }
    }

    // ---- normalize + write ----
    float inv0 = 1.0f / l0, inv1 = 1.0f / l1;
    int row0 = tok0 + mrow, row1 = row0 + 8;
    #pragma unroll
    for (int nf = 0; nf < 8; nf++) {
        int col = h * 64 + nf * 8 + 2 * t4;
        float2 v0; v0.x = of[nf][0] * inv0; v0.y = of[nf][1] * inv0;
        float2 v1; v1.x = of[nf][2] * inv1; v1.y = of[nf][3] * inv1;
        *(float2*)(outp + (size_t)row0 * D_MODEL + col) = v0;
        *(float2*)(outp + (size_t)row1 * D_MODEL + col) = v1;
    }
}

// ---------------- launcher ----------------
extern "C" void kernel_launch(void* const* d_in, const int* in_sizes, int n_in,
                              void* d_out, int out_size)
{
    const float* x      = (const float*)d_in[0];
    const float* qkv_w  = (const float*)d_in[1];
    const float* qkv_b  = (const float*)d_in[2];
    const float* out_w  = (const float*)d_in[3];
    const float* out_b  = (const float*)d_in[4];
    const float* ffn1_w = (const float*)d_in[5];
    const float* ffn1_b = (const float*)d_in[6];
    const float* ffn2_w = (const float*)d_in[7];
    const float* ffn2_b = (const float*)d_in[8];
    const float* ln1_g  = (const float*)d_in[9];
    const float* ln1_b  = (const float*)d_in[10];
    const float* ln2_g  = (const float*)d_in[11];
    const float* ln2_b  = (const float*)d_in[12];
    float* outp = (float*)d_out;

    float *normed, *qkvb, *attn, *x1, *hb;
    cudaGetSymbolAddress((void**)&normed, g_normed);
    cudaGetSymbolAddress((void**)&qkvb,   g_qkv);
    cudaGetSymbolAddress((void**)&attn,   g_attn);
    cudaGetSymbolAddress((void**)&x1,     g_x1);
    cudaGetSymbolAddress((void**)&hb,     g_h);

    cudaFuncSetAttribute(flash_tc,
                         cudaFuncAttributeMaxDynamicSharedMemorySize, FLASH_SMEM);

    // 1) LN1
    ln_kernel<<<NTOK, 256>>>(x, ln1_g, ln1_b, normed);
    // 2) QKV projection
    gemm_bf16<0><<<dim3(3 * D_MODEL / 128, NTOK / 128), 256>>>(
        normed, qkv_w, qkv_b, nullptr, qkvb, NTOK, 3 * D_MODEL, D_MODEL);
    // 3) causal flash attention (tf32 tensor cores)
    flash_tc<<<dim3(SEQ / FQ, NHEAD, BATCH), 256, FLASH_SMEM>>>(qkvb, attn);
    // 4) out projection + residual(x) -> x1
    gemm_bf16<2><<<dim3(D_MODEL / 128, NTOK / 128), 256>>>(
        attn, out_w, out_b, x, x1, NTOK, D_MODEL, D_MODEL);
    // 5) LN2
    ln_kernel<<<NTOK, 256>>>(x1, ln2_g, ln2_b, normed);
    // 6) FFN1 + GELU
    gemm_bf16<1><<<dim3(DFF / 128, NTOK / 128), 256>>>(
        normed, ffn1_w, ffn1_b, nullptr, hb, NTOK, DFF, D_MODEL);
    // 7) FFN2 + residual(x1) -> out
    gemm_bf16<2><<<dim3(D_MODEL / 128, NTOK / 128), 256>>>(
        hb, ffn2_w, ffn2_b, x1, outp, NTOK, D_MODEL, DFF);
}

// round 6
// speedup vs baseline: 5.4371x; 1.2480x over previous
#include <cuda_runtime.h>
#include <cuda_bf16.h>
#include <math.h>
#include <stdint.h>

#define D_MODEL 1024
#define SEQ     2048
#define BATCH   4
#define NTOK    (BATCH*SEQ)      // 8192
#define NHEAD   16
#define HDIM    64
#define DFF     4096

// ---------------- scratch (alloc-free: __device__ globals) ----------------
__device__ float         g_qkv [(size_t)NTOK * 3 * D_MODEL];   // 96 MB fp32
__device__ float         g_x1  [(size_t)NTOK * D_MODEL];       // 32 MB fp32
__device__ __nv_bfloat16 g_nrm [(size_t)NTOK * D_MODEL];       // 16 MB
__device__ __nv_bfloat16 g_attn[(size_t)NTOK * D_MODEL];       // 16 MB
__device__ __nv_bfloat16 g_h   [(size_t)NTOK * DFF];           // 64 MB
__device__ __nv_bfloat16 g_wq  [(size_t)D_MODEL * 3 * D_MODEL];
__device__ __nv_bfloat16 g_wo  [(size_t)D_MODEL * D_MODEL];
__device__ __nv_bfloat16 g_w1  [(size_t)D_MODEL * DFF];
__device__ __nv_bfloat16 g_w2  [(size_t)DFF * D_MODEL];

// ---------------- helpers ----------------
__device__ __forceinline__ float gelu_exact(float x) {
    return 0.5f * x * (1.0f + erff(x * 0.70710678118654752f));
}
__device__ __forceinline__ uint2 f4_to_bf16x4(float4 v) {
    __nv_bfloat162 lo = __floats2bfloat162_rn(v.x, v.y);
    __nv_bfloat162 hi = __floats2bfloat162_rn(v.z, v.w);
    uint2 r;
    r.x = *(uint32_t*)&lo;
    r.y = *(uint32_t*)&hi;
    return r;
}
__device__ __forceinline__ uint32_t f2_to_bf16x2(float a, float b) {
    __nv_bfloat162 p = __floats2bfloat162_rn(a, b);
    return *(uint32_t*)&p;
}
__device__ __forceinline__ uint32_t f2tf32(float x) {
    uint32_t r;
    asm("cvt.rna.tf32.f32 %0, %1;" : "=r"(r) : "f"(x));
    return r;
}
__device__ __forceinline__ void ldsm_x4(uint32_t& r0, uint32_t& r1,
                                        uint32_t& r2, uint32_t& r3,
                                        const void* p) {
    uint32_t a = (uint32_t)__cvta_generic_to_shared(p);
    asm volatile("ldmatrix.sync.aligned.m8n8.x4.shared.b16 {%0,%1,%2,%3}, [%4];"
                 : "=r"(r0), "=r"(r1), "=r"(r2), "=r"(r3) : "r"(a));
}
__device__ __forceinline__ void ldsm_x4_t(uint32_t& r0, uint32_t& r1,
                                          uint32_t& r2, uint32_t& r3,
                                          const void* p) {
    uint32_t a = (uint32_t)__cvta_generic_to_shared(p);
    asm volatile("ldmatrix.sync.aligned.m8n8.x4.trans.shared.b16 {%0,%1,%2,%3}, [%4];"
                 : "=r"(r0), "=r"(r1), "=r"(r2), "=r"(r3) : "r"(a));
}
__device__ __forceinline__ void cp16(void* dst, const void* src) {
    uint32_t d = (uint32_t)__cvta_generic_to_shared(dst);
    asm volatile("cp.async.cg.shared.global [%0], [%1], 16;" :: "r"(d), "l"(src));
}

// ---------------- fp32 -> bf16 convert (weights) ----------------
__global__ void __launch_bounds__(256) cvt_kernel(
    const float4* __restrict__ src, uint2* __restrict__ dst, int n4)
{
    int i = blockIdx.x * 256 + threadIdx.x;
    if (i < n4) dst[i] = f4_to_bf16x4(src[i]);
}

// ---------------- LayerNorm -> bf16 ----------
__global__ void __launch_bounds__(256) ln_kernel(
    const float* __restrict__ x, const float* __restrict__ g,
    const float* __restrict__ b, __nv_bfloat16* __restrict__ y)
{
    int t = blockIdx.x;
    int tid = threadIdx.x;
    const float4* row = (const float4*)(x + (size_t)t * D_MODEL);
    float4 v = row[tid];
    float s  = v.x + v.y + v.z + v.w;
    float sq = v.x*v.x + v.y*v.y + v.z*v.z + v.w*v.w;
    #pragma unroll
    for (int o = 16; o > 0; o >>= 1) {
        s  += __shfl_xor_sync(0xffffffffu, s,  o);
        sq += __shfl_xor_sync(0xffffffffu, sq, o);
    }
    __shared__ float ss[8], ssq[8];
    int w = tid >> 5, l = tid & 31;
    if (l == 0) { ss[w] = s; ssq[w] = sq; }
    __syncthreads();
    if (w == 0) {
        s  = (l < 8) ? ss[l]  : 0.f;
        sq = (l < 8) ? ssq[l] : 0.f;
        #pragma unroll
        for (int o = 4; o > 0; o >>= 1) {
            s  += __shfl_xor_sync(0xffffffffu, s,  o);
            sq += __shfl_xor_sync(0xffffffffu, sq, o);
        }
        if (l == 0) { ss[0] = s; ssq[0] = sq; }
    }
    __syncthreads();
    float mean = ss[0] * (1.0f / D_MODEL);
    float var  = ssq[0] * (1.0f / D_MODEL) - mean * mean;
    float rstd = rsqrtf(var + 1e-5f);
    float4 gg = ((const float4*)g)[tid];
    float4 bb = ((const float4*)b)[tid];
    float4 o4;
    o4.x = (v.x - mean) * rstd * gg.x + bb.x;
    o4.y = (v.y - mean) * rstd * gg.y + bb.y;
    o4.z = (v.z - mean) * rstd * gg.z + bb.z;
    o4.w = (v.w - mean) * rstd * gg.w + bb.w;
    ((uint2*)(y + (size_t)t * D_MODEL))[tid] = f4_to_bf16x4(o4);
}

// ---------------- bf16 GEMM, cp.async 3-stage pipeline ----------------------
// C[M,N] = A[M,K] @ B[K,N] + bias (+GELU | +residual), fp32 accumulate.
// A, B bf16 in gmem. CTA 128x128, BK=32, 8 warps (2x4), warp tile 64x32.
// A smem [m][k] stride 40 bf16; B smem [k][n] stride 136 bf16 (LDSM clean).
#define ASTR 40
#define BSTR 136
#define GSTAGE 3
#define GEMM_SMEM (GSTAGE * (128 * ASTR + 32 * BSTR) * 2)   // 56832 B

template<int EPI, int OUTBF>  // EPI: 0 bias, 1 bias+gelu, 2 bias+residual
__global__ void __launch_bounds__(256, 2) gemm_bf16(
    const __nv_bfloat16* __restrict__ A, const __nv_bfloat16* __restrict__ B,
    const float* __restrict__ bias, const float* __restrict__ Rsd,
    void* __restrict__ Cout, int M, int N, int K)
{
    extern __shared__ __nv_bfloat16 dynsm[];
    __nv_bfloat16* Asm = dynsm;                        // [GSTAGE][128*ASTR]
    __nv_bfloat16* Bsm = dynsm + GSTAGE * 128 * ASTR;  // [GSTAGE][32*BSTR]

    const int tid  = threadIdx.x;
    const int lane = tid & 31, warp = tid >> 5;
    const int wm = warp >> 2, wn = warp & 3;
    const int g  = lane >> 2, t4 = lane & 3;
    const int l15 = lane & 15, lhi = (lane >> 4) << 3;
    const int m0 = blockIdx.y * 128, n0 = blockIdx.x * 128;

    float acc[4][4][4];
    #pragma unroll
    for (int i = 0; i < 4; i++)
        #pragma unroll
        for (int j = 0; j < 4; j++)
            #pragma unroll
            for (int r = 0; r < 4; r++) acc[i][j][r] = 0.f;

    // loaders: A rows (tid>>2), +64; chunk col (tid&3)*8 of BK=32.
    //          B rows (tid>>4), +16; chunk col (tid&15)*8 of 128.
    const int ar = tid >> 2,  ac8 = (tid & 3) * 8;
    const int br = tid >> 4,  bc8 = (tid & 15) * 8;
    const __nv_bfloat16* Abase = A + (size_t)(m0 + ar) * K + ac8;
    const __nv_bfloat16* Bbase = B + n0 + bc8;

    auto load_stage = [&](int s, int k0) {
        __nv_bfloat16* as = Asm + s * 128 * ASTR;
        __nv_bfloat16* bs = Bsm + s * 32 * BSTR;
        cp16(&as[(ar     ) * ASTR + ac8], Abase + k0);
        cp16(&as[(ar + 64) * ASTR + ac8], Abase + (size_t)64 * K + k0);
        cp16(&bs[(br     ) * BSTR + bc8], Bbase + (size_t)(k0 + br) * N);
        cp16(&bs[(br + 16) * BSTR + bc8], Bbase + (size_t)(k0 + br + 16) * N);
    };

    load_stage(0, 0);
    asm volatile("cp.async.commit_group;");
    load_stage(1, 32);
    asm volatile("cp.async.commit_group;");

    int buf = 0;
    for (int k0 = 0; k0 < K; k0 += 32) {
        asm volatile("cp.async.wait_group 1;");
        __syncthreads();

        const __nv_bfloat16* a  = Asm + buf * 128 * ASTR;
        const __nv_bfloat16* bs = Bsm + buf * 32 * BSTR;
        #pragma unroll
        for (int ks = 0; ks < 2; ks++) {
            const int kb = ks * 16;
            uint32_t af[4][4];
            #pragma unroll
            for (int mt = 0; mt < 4; mt++)
                ldsm_x4(af[mt][0], af[mt][1], af[mt][2], af[mt][3],
                        &a[(wm * 64 + mt * 16 + l15) * ASTR + kb + lhi]);
            uint32_t bf_[4][2];
            #pragma unroll
            for (int ntp = 0; ntp < 2; ntp++) {
                uint32_t r0, r1, r2, r3;
                ldsm_x4_t(r0, r1, r2, r3,
                          &bs[(kb + l15) * BSTR + wn * 32 + ntp * 16 + lhi]);
                bf_[2 * ntp][0] = r0;     bf_[2 * ntp][1] = r1;
                bf_[2 * ntp + 1][0] = r2; bf_[2 * ntp + 1][1] = r3;
            }
            #pragma unroll
            for (int mt = 0; mt < 4; mt++)
                #pragma unroll
                for (int nt = 0; nt < 4; nt++)
                    asm volatile(
                        "mma.sync.aligned.m16n8k16.row.col.f32.bf16.bf16.f32 "
                        "{%0,%1,%2,%3}, {%4,%5,%6,%7}, {%8,%9}, {%0,%1,%2,%3};"
                        : "+f"(acc[mt][nt][0]), "+f"(acc[mt][nt][1]),
                          "+f"(acc[mt][nt][2]), "+f"(acc[mt][nt][3])
                        : "r"(af[mt][0]), "r"(af[mt][1]),
                          "r"(af[mt][2]), "r"(af[mt][3]),
                          "r"(bf_[nt][0]), "r"(bf_[nt][1]));
        }

        if (k0 + 64 < K) {
            int s = buf + 2; if (s >= GSTAGE) s -= GSTAGE;
            load_stage(s, k0 + 64);
        }
        asm volatile("cp.async.commit_group;");
        buf = (buf + 1 == GSTAGE) ? 0 : buf + 1;
    }

    // epilogue: fragment c0:(g, 2t4) c1:(g, 2t4+1) c2:(g+8, 2t4) c3:(g+8, 2t4+1)
    #pragma unroll
    for (int mt = 0; mt < 4; mt++) {
        #pragma unroll
        for (int nt = 0; nt < 4; nt++) {
            int row = m0 + wm * 64 + mt * 16 + g;
            int col = n0 + wn * 32 + nt * 8 + t4 * 2;
            float2 bb = *(const float2*)(bias + col);
            #pragma unroll
            for (int h = 0; h < 2; h++) {
                int r = row + h * 8;
                float2 v;
                v.x = acc[mt][nt][h * 2 + 0] + bb.x;
                v.y = acc[mt][nt][h * 2 + 1] + bb.y;
                if (EPI == 1) { v.x = gelu_exact(v.x); v.y = gelu_exact(v.y); }
                if (EPI == 2) {
                    float2 rr = *(const float2*)(Rsd + (size_t)r * N + col);
                    v.x += rr.x; v.y += rr.y;
                }
                if (OUTBF) {
                    __nv_bfloat16* C = (__nv_bfloat16*)Cout;
                    *(uint32_t*)&C[(size_t)r * N + col] = f2_to_bf16x2(v.x, v.y);
                } else {
                    float* C = (float*)Cout;
                    *(float2*)(C + (size_t)r * N + col) = v;
                }
            }
        }
    }
}

// ---------------- Flash attention, tf32 tensor cores (out -> bf16) ----------
#define FQ   128
#define FK   64
#define QSTR 68
#define KSTR 72
#define FLASH_SMEM ((FQ*QSTR + FK*KSTR + FK*KSTR) * 4)   // 71680 B

__global__ void __launch_bounds__(256, 2) flash_tc(
    const float* __restrict__ qkv, __nv_bfloat16* __restrict__ outp)
{
    extern __shared__ uint32_t smu[];
    uint32_t* QP  = smu;
    uint32_t* KsT = smu + FQ * QSTR;
    uint32_t* Vs  = KsT + FK * KSTR;

    const int tid  = threadIdx.x;
    const int lane = tid & 31, w = tid >> 5;
    const int g = lane >> 2, t4 = lane & 3;
    const int qt = (SEQ / FQ - 1) - blockIdx.x;
    const int h  = blockIdx.y, b = blockIdx.z;
    const int tok0 = b * SEQ + qt * FQ;
    const int mrow = w * 16 + g;

    {
        size_t qbase = (size_t)tok0 * 3072 + h * 64;
        #pragma unroll
        for (int p = 0; p < 8; p++) {
            int f = tid + p * 256;
            int r = f >> 4, c = (f & 15) * 4;
            float4 v = *(const float4*)(qkv + qbase + (size_t)r * 3072 + c);
            uint32_t* dst = &QP[r * QSTR + c];
            dst[0] = __float_as_uint(v.x * 0.125f);
            dst[1] = __float_as_uint(v.y * 0.125f);
            dst[2] = __float_as_uint(v.z * 0.125f);
            dst[3] = __float_as_uint(v.w * 0.125f);
        }
    }
    __syncthreads();

    uint32_t qf[8][4];
    #pragma unroll
    for (int ks = 0; ks < 8; ks++) {
        int kb = ks * 8;
        qf[ks][0] = f2tf32(__uint_as_float(QP[(mrow    ) * QSTR + kb + t4]));
        qf[ks][1] = f2tf32(__uint_as_float(QP[(mrow + 8) * QSTR + kb + t4]));
        qf[ks][2] = f2tf32(__uint_as_float(QP[(mrow    ) * QSTR + kb + t4 + 4]));
        qf[ks][3] = f2tf32(__uint_as_float(QP[(mrow + 8) * QSTR + kb + t4 + 4]));
    }

    float m0r = -1e30f, m1r = -1e30f, l0 = 0.f, l1 = 0.f;
    float of[8][4];
    #pragma unroll
    for (int nf = 0; nf < 8; nf++)
        #pragma unroll
        for (int j = 0; j < 4; j++) of[nf][j] = 0.f;

    const int qrow0 = qt * FQ + mrow;
    const int qrow1 = qrow0 + 8;
    const int nkt = 2 * qt + 2;

    for (int kt = 0; kt < nkt; kt++) {
        __syncthreads();
        {
            int ktok0 = b * SEQ + kt * FK;
            size_t kbase = (size_t)ktok0 * 3072 + 1024 + h * 64;
            size_t vbase = kbase + 1024;
            #pragma unroll
            for (int p = 0; p < 4; p++) {
                int f = tid + p * 256;
                int kr = f & 63, kc = (f >> 6) * 4;
                float4 kv = *(const float4*)(qkv + kbase + (size_t)kr * 3072 + kc);
                KsT[(kc + 0) * KSTR + kr] = f2tf32(kv.x);
                KsT[(kc + 1) * KSTR + kr] = f2tf32(kv.y);
                KsT[(kc + 2) * KSTR + kr] = f2tf32(kv.z);
                KsT[(kc + 3) * KSTR + kr] = f2tf32(kv.w);
                int vr = f >> 4, vc = (f & 15) * 4;
                float4 vv = *(const float4*)(qkv + vbase + (size_t)vr * 3072 + vc);
                uint4 vb;
                vb.x = f2tf32(vv.x); vb.y = f2tf32(vv.y);
                vb.z = f2tf32(vv.z); vb.w = f2tf32(vv.w);
                *(uint4*)&Vs[vr * KSTR + vc] = vb;
            }
        }
        __syncthreads();

        float sc[8][4];
        #pragma unroll
        for (int nf = 0; nf < 8; nf++)
            #pragma unroll
            for (int j = 0; j < 4; j++) sc[nf][j] = 0.f;
        #pragma unroll
        for (int ks = 0; ks < 8; ks++) {
            int kb = ks * 8;
            uint32_t bf[8][2];
            #pragma unroll
            for (int nf = 0; nf < 8; nf++) {
                bf[nf][0] = KsT[(kb + t4    ) * KSTR + nf * 8 + g];
                bf[nf][1] = KsT[(kb + t4 + 4) * KSTR + nf * 8 + g];
            }
            #pragma unroll
            for (int nf = 0; nf < 8; nf++)
                asm volatile(
                    "mma.sync.aligned.m16n8k8.row.col.f32.tf32.tf32.f32 "
                    "{%0,%1,%2,%3}, {%4,%5,%6,%7}, {%8,%9}, {%0,%1,%2,%3};"
                    : "+f"(sc[nf][0]), "+f"(sc[nf][1]),
                      "+f"(sc[nf][2]), "+f"(sc[nf][3])
                    : "r"(qf[ks][0]), "r"(qf[ks][1]),
                      "r"(qf[ks][2]), "r"(qf[ks][3]),
                      "r"(bf[nf][0]), "r"(bf[nf][1]));
        }

        if (kt >= 2 * qt) {
            #pragma unroll
            for (int nf = 0; nf < 8; nf++) {
                int k0 = kt * FK + nf * 8 + 2 * t4;
                if (k0     > qrow0) sc[nf][0] = -1e30f;
                if (k0 + 1 > qrow0) sc[nf][1] = -1e30f;
                if (k0     > qrow1) sc[nf][2] = -1e30f;
                if (k0 + 1 > qrow1) sc[nf][3] = -1e30f;
            }
        }

        float mx0 = -1e30f, mx1 = -1e30f;
        #pragma unroll
        for (int nf = 0; nf < 8; nf++) {
            mx0 = fmaxf(mx0, fmaxf(sc[nf][0], sc[nf][1]));
            mx1 = fmaxf(mx1, fmaxf(sc[nf][2], sc[nf][3]));
        }
        mx0 = fmaxf(mx0, __shfl_xor_sync(0xffffffffu, mx0, 1));
        mx0 = fmaxf(mx0, __shfl_xor_sync(0xffffffffu, mx0, 2));
        mx1 = fmaxf(mx1, __shfl_xor_sync(0xffffffffu, mx1, 1));
        mx1 = fmaxf(mx1, __shfl_xor_sync(0xffffffffu, mx1, 2));
        float nm0 = fmaxf(m0r, mx0), nm1 = fmaxf(m1r, mx1);
        float fac0 = __expf(m0r - nm0), fac1 = __expf(m1r - nm1);
        m0r = nm0; m1r = nm1;

        float rs0 = 0.f, rs1 = 0.f;
        #pragma unroll
        for (int nf = 0; nf < 8; nf++) {
            float p00 = __expf(sc[nf][0] - nm0);
            float p01 = __expf(sc[nf][1] - nm0);
            float p10 = __expf(sc[nf][2] - nm1);
            float p11 = __expf(sc[nf][3] - nm1);
            rs0 += p00 + p01;
            rs1 += p10 + p11;
            int colb = nf * 8 + 2 * t4;
            uint2 w0; w0.x = f2tf32(p00); w0.y = f2tf32(p01);
            uint2 w1; w1.x = f2tf32(p10); w1.y = f2tf32(p11);
            *(uint2*)&QP[(mrow    ) * QSTR + colb] = w0;
            *(uint2*)&QP[(mrow + 8) * QSTR + colb] = w1;
        }
        rs0 += __shfl_xor_sync(0xffffffffu, rs0, 1);
        rs0 += __shfl_xor_sync(0xffffffffu, rs0, 2);
        rs1 += __shfl_xor_sync(0xffffffffu, rs1, 1);
        rs1 += __shfl_xor_sync(0xffffffffu, rs1, 2);
        l0 = l0 * fac0 + rs0;
        l1 = l1 * fac1 + rs1;
        #pragma unroll
        for (int nf = 0; nf < 8; nf++) {
            of[nf][0] *= fac0; of[nf][1] *= fac0;
            of[nf][2] *= fac1; of[nf][3] *= fac1;
        }
        __syncthreads();

        #pragma unroll
        for (int ks = 0; ks < 8; ks++) {
            int kb = ks * 8;
            uint32_t af[4];
            af[0] = QP[(mrow    ) * QSTR + kb + t4];
            af[1] = QP[(mrow + 8) * QSTR + kb + t4];
            af[2] = QP[(mrow    ) * QSTR + kb + t4 + 4];
            af[3] = QP[(mrow + 8) * QSTR + kb + t4 + 4];
            uint32_t bf[8][2];
            #pragma unroll
            for (int nf = 0; nf < 8; nf++) {
                bf[nf][0] = Vs[(kb + t4    ) * KSTR + nf * 8 + g];
                bf[nf][1] = Vs[(kb + t4 + 4) * KSTR + nf * 8 + g];
            }
            #pragma unroll
            for (int nf = 0; nf < 8; nf++)
                asm volatile(
                    "mma.sync.aligned.m16n8k8.row.col.f32.tf32.tf32.f32 "
                    "{%0,%1,%2,%3}, {%4,%5,%6,%7}, {%8,%9}, {%0,%1,%2,%3};"
                    : "+f"(of[nf][0]), "+f"(of[nf][1]),
                      "+f"(of[nf][2]), "+f"(of[nf][3])
                    : "r"(af[0]), "r"(af[1]), "r"(af[2]), "r"(af[3]),
                      "r"(bf[nf][0]), "r"(bf[nf][1]));
        }
    }

    float inv0 = 1.0f / l0, inv1 = 1.0f / l1;
    int row0 = tok0 + mrow, row1 = row0 + 8;
    #pragma unroll
    for (int nf = 0; nf < 8; nf++) {
        int col = h * 64 + nf * 8 + 2 * t4;
        *(uint32_t*)&outp[(size_t)row0 * D_MODEL + col] =
            f2_to_bf16x2(of[nf][0] * inv0, of[nf][1] * inv0);
        *(uint32_t*)&outp[(size_t)row1 * D_MODEL + col] =
            f2_to_bf16x2(of[nf][2] * inv1, of[nf][3] * inv1);
    }
}

// ---------------- launcher ----------------
extern "C" void kernel_launch(void* const* d_in, const int* in_sizes, int n_in,
                              void* d_out, int out_size)
{
    const float* x      = (const float*)d_in[0];
    const float* qkv_w  = (const float*)d_in[1];
    const float* qkv_b  = (const float*)d_in[2];
    const float* out_w  = (const float*)d_in[3];
    const float* out_b  = (const float*)d_in[4];
    const float* ffn1_w = (const float*)d_in[5];
    const float* ffn1_b = (const float*)d_in[6];
    const float* ffn2_w = (const float*)d_in[7];
    const float* ffn2_b = (const float*)d_in[8];
    const float* ln1_g  = (const float*)d_in[9];
    const float* ln1_b  = (const float*)d_in[10];
    const float* ln2_g  = (const float*)d_in[11];
    const float* ln2_b  = (const float*)d_in[12];
    float* outp = (float*)d_out;

    float *qkvb, *x1;
    __nv_bfloat16 *nrm, *attn, *hb, *wq, *wo, *w1, *w2;
    cudaGetSymbolAddress((void**)&qkvb, g_qkv);
    cudaGetSymbolAddress((void**)&x1,   g_x1);
    cudaGetSymbolAddress((void**)&nrm,  g_nrm);
    cudaGetSymbolAddress((void**)&attn, g_attn);
    cudaGetSymbolAddress((void**)&hb,   g_h);
    cudaGetSymbolAddress((void**)&wq,   g_wq);
    cudaGetSymbolAddress((void**)&wo,   g_wo);
    cudaGetSymbolAddress((void**)&w1,   g_w1);
    cudaGetSymbolAddress((void**)&w2,   g_w2);

    cudaFuncSetAttribute(flash_tc,
                         cudaFuncAttributeMaxDynamicSharedMemorySize, FLASH_SMEM);
    cudaFuncSetAttribute(gemm_bf16<0,0>,
                         cudaFuncAttributeMaxDynamicSharedMemorySize, GEMM_SMEM);
    cudaFuncSetAttribute(gemm_bf16<1,1>,
                         cudaFuncAttributeMaxDynamicSharedMemorySize, GEMM_SMEM);
    cudaFuncSetAttribute(gemm_bf16<2,0>,
                         cudaFuncAttributeMaxDynamicSharedMemorySize, GEMM_SMEM);

    // 0) convert weights fp32 -> bf16
    cvt_kernel<<<(D_MODEL*3*D_MODEL/4 + 255)/256, 256>>>(
        (const float4*)qkv_w, (uint2*)wq, D_MODEL*3*D_MODEL/4);
    cvt_kernel<<<(D_MODEL*D_MODEL/4 + 255)/256, 256>>>(
        (const float4*)out_w, (uint2*)wo, D_MODEL*D_MODEL/4);
    cvt_kernel<<<(D_MODEL*DFF/4 + 255)/256, 256>>>(
        (const float4*)ffn1_w, (uint2*)w1, D_MODEL*DFF/4);
    cvt_kernel<<<(DFF*D_MODEL/4 + 255)/256, 256>>>(
        (const float4*)ffn2_w, (uint2*)w2, DFF*D_MODEL/4);

    // 1) LN1 -> bf16
    ln_kernel<<<NTOK, 256>>>(x, ln1_g, ln1_b, nrm);
    // 2) QKV projection -> fp32 qkvb
    gemm_bf16<0,0><<<dim3(3 * D_MODEL / 128, NTOK / 128), 256, GEMM_SMEM>>>(
        nrm, wq, qkv_b, nullptr, qkvb, NTOK, 3 * D_MODEL, D_MODEL);
    // 3) flash attention (tf32) -> bf16 attn
    flash_tc<<<dim3(SEQ / FQ, NHEAD, BATCH), 256, FLASH_SMEM>>>(qkvb, attn);
    // 4) out projection + residual(x) -> fp32 x1
    gemm_bf16<2,0><<<dim3(D_MODEL / 128, NTOK / 128), 256, GEMM_SMEM>>>(
        attn, wo, out_b, x, x1, NTOK, D_MODEL, D_MODEL);
    // 5) LN2 -> bf16
    ln_kernel<<<NTOK, 256>>>(x1, ln2_g, ln2_b, nrm);
    // 6) FFN1 + GELU -> bf16 hb
    gemm_bf16<1,1><<<dim3(DFF / 128, NTOK / 128), 256, GEMM_SMEM>>>(
        nrm, w1, ffn1_b, nullptr, hb, NTOK, DFF, D_MODEL);
    // 7) FFN2 + residual(x1) -> fp32 out
    gemm_bf16<2,0><<<dim3(D_MODEL / 128, NTOK / 128), 256, GEMM_SMEM>>>(
        hb, w2, ffn2_b, x1, outp, NTOK, D_MODEL, DFF);
}